// round 2
// baseline (speedup 1.0000x reference)
#include <cuda_runtime.h>

#define B_ 2
#define L_ 2048
#define D_ 1024
#define H_ 8
#define QK_ 128
#define V_ 128
#define ML_ (B_*L_)   // 4096 rows

// ---------------- scratch (device globals: no allocation allowed) ----------------
__device__ float g_q[(long)H_*B_*L_*QK_];
__device__ float g_k[(long)H_*B_*L_*QK_];
__device__ float g_v[(long)H_*B_*L_*V_];
__device__ float g_r[(long)B_*L_*H_*V_];   // retention result, (b,l,h,v); groupnorm in-place
__device__ float g_g[(long)B_*L_*H_*V_];   // gate projection
__device__ float g_x[(long)B_*L_*H_*V_];   // gate * rn

__device__ __forceinline__ float* dev_buf(int id) {
    switch (id) {
        case 0: return g_q;
        case 1: return g_k;
        case 2: return g_v;
        case 3: return g_r;
        case 4: return g_g;
        default: return g_x;
    }
}

// ---------------- generic fp32 GEMM: C[M,N] = A[M,K] * B[K,N] ----------------
// 64x64 tile, 256 threads, 4x4 per-thread microtile, K-chunk 16.
// a_id/b_id/c_id < 0 -> use external pointer; else device scratch buffer.
__global__ __launch_bounds__(256) void gemm_tiled(
    const float* __restrict__ Aext, const float* __restrict__ Bext, float* __restrict__ Cext,
    int a_id, int b_id, int c_id,
    int Kdim, int ldb, int ldc, long strideB, long strideC)
{
    const float* A  = (a_id < 0) ? Aext : dev_buf(a_id);
    const float* Bm = ((b_id < 0) ? Bext : dev_buf(b_id)) + (long)blockIdx.z * strideB;
    float*       C  = ((c_id < 0) ? Cext : dev_buf(c_id)) + (long)blockIdx.z * strideC;

    __shared__ float As[16][72];   // [k][m], padded (row = 288B, 16B aligned)
    __shared__ float Bs[16][64];   // [k][n]

    const int tid = threadIdx.x;
    const int ty = tid >> 4, tx = tid & 15;
    const long m0 = (long)blockIdx.y * 64;
    const int  n0 = blockIdx.x * 64;

    float acc[4][4] = {};

    const int am = tid >> 2, ak = (tid & 3) << 2;   // A loader: one float4 per thread
    const int bk = tid >> 4, bn = (tid & 15) << 2;  // B loader: one float4 per thread
    const float* Aptr = A + (m0 + am) * (long)Kdim + ak;
    const float* Bptr = Bm + (long)bk * ldb + n0 + bn;

    for (int k0 = 0; k0 < Kdim; k0 += 16) {
        float4 a4 = *reinterpret_cast<const float4*>(Aptr);
        float4 b4 = *reinterpret_cast<const float4*>(Bptr);
        As[ak + 0][am] = a4.x; As[ak + 1][am] = a4.y;
        As[ak + 2][am] = a4.z; As[ak + 3][am] = a4.w;
        *reinterpret_cast<float4*>(&Bs[bk][bn]) = b4;
        __syncthreads();
        #pragma unroll
        for (int kk = 0; kk < 16; kk++) {
            float4 av = *reinterpret_cast<const float4*>(&As[kk][ty << 2]);
            float4 bv = *reinterpret_cast<const float4*>(&Bs[kk][tx << 2]);
            float a[4] = {av.x, av.y, av.z, av.w};
            float b[4] = {bv.x, bv.y, bv.z, bv.w};
            #pragma unroll
            for (int i = 0; i < 4; i++)
                #pragma unroll
                for (int j = 0; j < 4; j++)
                    acc[i][j] += a[i] * b[j];
        }
        __syncthreads();
        Aptr += 16;
        Bptr += (long)16 * ldb;
    }
    #pragma unroll
    for (int i = 0; i < 4; i++) {
        float4 o = make_float4(acc[i][0], acc[i][1], acc[i][2], acc[i][3]);
        *reinterpret_cast<float4*>(C + (m0 + (ty << 2) + i) * (long)ldc + n0 + (tx << 2)) = o;
    }
}

// ---------------- RoPE on q (+angle) and k (-angle), in place ----------------
__global__ __launch_bounds__(256) void rope_kernel(const float* __restrict__ times)
{
    int idx = blockIdx.x * 256 + threadIdx.x;   // over H*B*L*64 pairs
    int pair = idx & 63;
    int rest = idx >> 6;            // linear (h,b,l) matching g_q layout
    int l  = rest & (L_ - 1);
    int bh = rest >> 11;            // L = 2048
    int b  = bh & (B_ - 1);

    float t = times[b * L_ + l];
    // theta_i = 10000^(-2 i / 128) = 2^(-(i/64) * log2(10000))
    float theta = exp2f(-13.287712379549449f * (float)pair * (1.0f / 64.0f));
    float s, c;
    sincosf(t * theta, &s, &c);

    long base = ((long)rest << 7) + (pair << 1);
    float q0 = g_q[base], q1 = g_q[base + 1];
    g_q[base]     = c * q0 - s * q1;
    g_q[base + 1] = c * q1 + s * q0;
    float k0 = g_k[base], k1 = g_k[base + 1];
    g_k[base]     = c * k0 + s * k1;
    g_k[base + 1] = c * k1 - s * k0;
}

// ---------------- causal retention: O = (Q K^T ⊙ decay) V ----------------
// block = (i-tile of 64 rows, b, h), 256 threads.
__global__ __launch_bounds__(256) void retention_kernel()
{
    const int h  = blockIdx.z;
    const int b  = blockIdx.y;
    const int i0 = blockIdx.x * 64;

    const long hb = (long)(h * B_ + b);
    const float* Q  = g_q + hb * L_ * QK_;
    const float* K  = g_k + hb * L_ * QK_;
    const float* Vv = g_v + hb * L_ * V_;

    const float gamma = 1.0f - exp2f(-5.0f - (float)h);
    const float lg = log2f(gamma);

    const int tid = threadIdx.x;
    const int ty = tid >> 4, tx = tid & 15;

    __shared__ float Ssm[64][72];
    __shared__ float ubuf[2 * 32 * 72];         // phase1: Qs/Ks [32][72]; phase2: Vs [32][132]
    float* Qs = ubuf;
    float* Ks = ubuf + 32 * 72;
    float* Vs = ubuf;                           // 32*132 = 4224 <= 4608 floats

    // decay factorization: gamma^(ig-jg) = gamma^(i0-j0) * gamma^r * gamma^(-c)
    float powr[4], powc[4];
    #pragma unroll
    for (int i = 0; i < 4; i++) {
        powr[i] = exp2f(lg * (float)((ty << 2) + i));
        powc[i] = exp2f(-lg * (float)((tx << 2) + i));
    }

    float oacc[4][8] = {};   // rows ty*4+i, cols tx + 16*j (conflict-free V reads)

    for (int j0 = 0; j0 <= i0; j0 += 64) {
        // ---- phase 1: S = Q_i K_j^T ----
        float sacc[4][4] = {};
        #pragma unroll 1
        for (int kc = 0; kc < QK_; kc += 32) {
            #pragma unroll
            for (int rep = 0; rep < 2; rep++) {
                int idx = tid + rep * 256;          // 64x32 tile, transposed store
                int m  = idx >> 3;
                int k4 = (idx & 7) << 2;
                float4 qv = *reinterpret_cast<const float4*>(Q + (long)(i0 + m) * QK_ + kc + k4);
                Qs[(k4 + 0) * 72 + m] = qv.x; Qs[(k4 + 1) * 72 + m] = qv.y;
                Qs[(k4 + 2) * 72 + m] = qv.z; Qs[(k4 + 3) * 72 + m] = qv.w;
                float4 kv = *reinterpret_cast<const float4*>(K + (long)(j0 + m) * QK_ + kc + k4);
                Ks[(k4 + 0) * 72 + m] = kv.x; Ks[(k4 + 1) * 72 + m] = kv.y;
                Ks[(k4 + 2) * 72 + m] = kv.z; Ks[(k4 + 3) * 72 + m] = kv.w;
            }
            __syncthreads();
            #pragma unroll
            for (int kk = 0; kk < 32; kk++) {
                float4 av = *reinterpret_cast<const float4*>(&Qs[kk * 72 + (ty << 2)]);
                float4 bv = *reinterpret_cast<const float4*>(&Ks[kk * 72 + (tx << 2)]);
                float a[4] = {av.x, av.y, av.z, av.w};
                float bb[4] = {bv.x, bv.y, bv.z, bv.w};
                #pragma unroll
                for (int i = 0; i < 4; i++)
                    #pragma unroll
                    for (int j = 0; j < 4; j++)
                        sacc[i][j] += a[i] * bb[j];
            }
            __syncthreads();
        }

        // ---- decay + mask, stage S to smem ----
        const float base = exp2f(lg * (float)(i0 - j0));
        const bool diag = (j0 == i0);
        #pragma unroll
        for (int i = 0; i < 4; i++) {
            int r = (ty << 2) + i;
            #pragma unroll
            for (int j = 0; j < 4; j++) {
                int c = (tx << 2) + j;
                float sv = sacc[i][j] * (base * powr[i] * powc[j]);
                if (diag && c > r) sv = 0.0f;
                Ssm[r][c] = sv;
            }
        }
        __syncthreads();

        // ---- phase 2: O += S V_j ----
        #pragma unroll 1
        for (int vc = 0; vc < 64; vc += 32) {
            #pragma unroll
            for (int rep = 0; rep < 4; rep++) {
                int idx = tid + rep * 256;          // 32x128 tile
                int m  = idx >> 5;
                int k4 = (idx & 31) << 2;
                *reinterpret_cast<float4*>(&Vs[m * 132 + k4]) =
                    *reinterpret_cast<const float4*>(Vv + (long)(j0 + vc + m) * V_ + k4);
            }
            __syncthreads();
            #pragma unroll
            for (int kk = 0; kk < 32; kk++) {
                float a[4];
                #pragma unroll
                for (int i = 0; i < 4; i++) a[i] = Ssm[(ty << 2) + i][vc + kk];
                #pragma unroll
                for (int j = 0; j < 8; j++) {
                    float bvv = Vs[kk * 132 + tx + (j << 4)];
                    #pragma unroll
                    for (int i = 0; i < 4; i++) oacc[i][j] += a[i] * bvv;
                }
            }
            __syncthreads();
        }
    }

    // ---- epilogue: write (b, l, h, v) layout ----
    #pragma unroll
    for (int i = 0; i < 4; i++) {
        long row = ((long)(b * L_ + i0 + (ty << 2) + i) * H_ + h);
        #pragma unroll
        for (int j = 0; j < 8; j++)
            g_r[row * V_ + tx + (j << 4)] = oacc[i][j];
    }
}

// ---------------- group norm over V=128 per (b,l,h), in place ----------------
__global__ __launch_bounds__(256) void gnorm_kernel(const float* __restrict__ gn_w,
                                                    const float* __restrict__ gn_b)
{
    int g    = blockIdx.x * 8 + (threadIdx.x >> 5);   // group id in [0, B*L*H)
    int lane = threadIdx.x & 31;
    int h    = g & (H_ - 1);

    float* p = g_r + (long)g * V_;
    float4 x = *reinterpret_cast<float4*>(p + (lane << 2));

    float sum = x.x + x.y + x.z + x.w;
    #pragma unroll
    for (int off = 16; off; off >>= 1) sum += __shfl_xor_sync(~0u, sum, off);
    float mean = sum * (1.0f / 128.0f);

    float dx = x.x - mean, dy = x.y - mean, dz = x.z - mean, dw = x.w - mean;
    float sq = dx * dx + dy * dy + dz * dz + dw * dw;
    #pragma unroll
    for (int off = 16; off; off >>= 1) sq += __shfl_xor_sync(~0u, sq, off);
    float inv = rsqrtf(sq * (1.0f / 128.0f) + 1e-5f);

    const float* w  = gn_w + h * V_ + (lane << 2);
    const float* bb = gn_b + h * V_ + (lane << 2);
    x.x = dx * inv * w[0] + bb[0];
    x.y = dy * inv * w[1] + bb[1];
    x.z = dz * inv * w[2] + bb[2];
    x.w = dw * inv * w[3] + bb[3];
    *reinterpret_cast<float4*>(p + (lane << 2)) = x;
}

// ---------------- silu gate: x = g*sigmoid(g) * rn ----------------
__global__ __launch_bounds__(256) void gate_kernel()
{
    long idx = (long)blockIdx.x * 256 + threadIdx.x;
    float gv = g_g[idx];
    float sig = 1.0f / (1.0f + expf(-gv));
    g_x[idx] = gv * sig * g_r[idx];
}

// ---------------- launch ----------------
extern "C" void kernel_launch(void* const* d_in, const int* in_sizes, int n_in,
                              void* d_out, int out_size)
{
    const float* seq   = (const float*)d_in[0];
    const float* times = (const float*)d_in[1];
    const float* wq    = (const float*)d_in[2];
    const float* wk    = (const float*)d_in[3];
    const float* wv    = (const float*)d_in[4];
    const float* wg    = (const float*)d_in[5];
    const float* wo    = (const float*)d_in[6];
    const float* gnw   = (const float*)d_in[7];
    const float* gnb   = (const float*)d_in[8];
    float* out = (float*)d_out;

    // q/k/v projections: per-head [4096x1024] @ [1024x128]
    dim3 gProj(QK_ / 64, ML_ / 64, H_);
    gemm_tiled<<<gProj, 256>>>(seq, wq, nullptr, -1, -1, 0, D_, QK_, QK_,
                               (long)D_ * QK_, (long)ML_ * QK_);
    gemm_tiled<<<gProj, 256>>>(seq, wk, nullptr, -1, -1, 1, D_, QK_, QK_,
                               (long)D_ * QK_, (long)ML_ * QK_);
    gemm_tiled<<<gProj, 256>>>(seq, wv, nullptr, -1, -1, 2, D_, V_, V_,
                               (long)D_ * V_, (long)ML_ * V_);
    // gate projection: [4096x1024] @ [1024x1024]
    gemm_tiled<<<dim3(16, ML_ / 64, 1), 256>>>(seq, wg, nullptr, -1, -1, 4,
                                               D_, H_ * V_, H_ * V_, 0, 0);
    // rope
    rope_kernel<<<(H_ * B_ * L_ * 64) / 256, 256>>>(times);
    // retention
    retention_kernel<<<dim3(L_ / 64, B_, H_), 256>>>();
    // group norm
    gnorm_kernel<<<(B_ * L_ * H_) / 8, 256>>>(gnw, gnb);
    // silu gate * rn
    gate_kernel<<<(B_ * L_ * (H_ * V_)) / 256, 256>>>();
    // output GEMM: [4096x1024] @ [1024x1024] -> d_out
    gemm_tiled<<<dim3(16, ML_ / 64, 1), 256>>>(nullptr, wo, out, 5, -1, -1,
                                               H_ * V_, H_ * V_, H_ * V_, 0, 0);
}

// round 4
// speedup vs baseline: 1.7088x; 1.7088x over previous
#include <cuda_runtime.h>
#include <cuda_bf16.h>
#include <cstdint>

#define B_ 2
#define L_ 2048
#define D_ 1024
#define H_ 8
#define QK_ 128
#define V_ 128
#define ML_ (B_*L_)        // 4096 rows
#define NBIG 4096          // q|k|v|g column blocks
#define K3 3072            // tripled K for split-bf16

// ---------------- scratch (device globals: no allocation allowed) ----------------
__device__ __nv_bfloat16 g_acat[(long)ML_ * K3];    // seq split [Ah|Ah|Al]
__device__ __nv_bfloat16 g_bcat[(long)K3 * NBIG];   // weights split [Bh;Bl;Bh]
__device__ __nv_bfloat16 g_a2[(long)ML_ * K3];      // gate*rn split
__device__ __nv_bfloat16 g_b2[(long)K3 * 1024];     // w_o split
__device__ float g_c[(long)ML_ * NBIG];             // fused projection output [q|k|v|g]
__device__ float g_r[(long)ML_ * 1024];             // retention result (b,l,h,v)

// ---------------- mma helpers ----------------
__device__ __forceinline__ uint32_t smem_u32(const void* p) {
    return (uint32_t)__cvta_generic_to_shared(p);
}
__device__ __forceinline__ void ldmA(uint32_t* r, uint32_t addr) {
    asm volatile("ldmatrix.sync.aligned.m8n8.x4.shared.b16 {%0,%1,%2,%3}, [%4];"
                 : "=r"(r[0]), "=r"(r[1]), "=r"(r[2]), "=r"(r[3]) : "r"(addr));
}
__device__ __forceinline__ void ldmBT(uint32_t* r, uint32_t addr) {
    asm volatile("ldmatrix.sync.aligned.m8n8.x4.trans.shared.b16 {%0,%1,%2,%3}, [%4];"
                 : "=r"(r[0]), "=r"(r[1]), "=r"(r[2]), "=r"(r[3]) : "r"(addr));
}
__device__ __forceinline__ void mma16816(float* c, const uint32_t* a, const uint32_t* b) {
    asm volatile("mma.sync.aligned.m16n8k16.row.col.f32.bf16.bf16.f32 "
                 "{%0,%1,%2,%3},{%4,%5,%6,%7},{%8,%9},{%0,%1,%2,%3};"
                 : "+f"(c[0]), "+f"(c[1]), "+f"(c[2]), "+f"(c[3])
                 : "r"(a[0]), "r"(a[1]), "r"(a[2]), "r"(a[3]), "r"(b[0]), "r"(b[1]));
}

// ---------------- bf16 tensor-core GEMM: C[M,N] = A[M,K3] * B[K3,N] ----------------
// 128x128 block tile, 8 warps (2x4), 64x32 per warp, BK=32.
__global__ __launch_bounds__(256) void gemm_bf16(float* __restrict__ Cext, int which,
                                                 int Kdim, int ldb, int ldc)
{
    const __nv_bfloat16* A = (which == 0) ? g_acat : g_a2;
    const __nv_bfloat16* Bp = (which == 0) ? g_bcat : g_b2;
    float* C = (which == 0) ? g_c : Cext;

    __shared__ __nv_bfloat16 As[128][40];   // pitch 40 bf16 = 20 banks -> conflict-free ldmatrix
    __shared__ __nv_bfloat16 Bs[32][136];   // pitch 136 bf16 = 68 banks == 4 mod 32

    const int tid = threadIdx.x;
    const int warp = tid >> 5, lane = tid & 31;
    const int wm = (warp >> 2) * 64;        // warp M offset (2 warps)
    const int wn = (warp & 3) * 32;         // warp N offset (4 warps)
    const long m0 = (long)blockIdx.y * 128;
    const int  n0 = blockIdx.x * 128;

    float acc[4][4][4] = {};

    for (int k0 = 0; k0 < Kdim; k0 += 32) {
        #pragma unroll
        for (int rep = 0; rep < 2; rep++) {
            int idx = tid + rep * 256;
            int r  = idx >> 2, cg = (idx & 3) << 3;
            *reinterpret_cast<float4*>(&As[r][cg]) =
                *reinterpret_cast<const float4*>(A + (m0 + r) * (long)Kdim + k0 + cg);
            int rb = idx >> 4, cb = (idx & 15) << 3;
            *reinterpret_cast<float4*>(&Bs[rb][cb]) =
                *reinterpret_cast<const float4*>(Bp + (long)(k0 + rb) * ldb + n0 + cb);
        }
        __syncthreads();
        #pragma unroll
        for (int ks = 0; ks < 32; ks += 16) {
            uint32_t af[4][4], bfr[2][4];
            #pragma unroll
            for (int mi = 0; mi < 4; mi++)
                ldmA(af[mi], smem_u32(&As[wm + 16 * mi + (lane & 15)][ks + ((lane >> 4) << 3)]));
            #pragma unroll
            for (int nn = 0; nn < 2; nn++)
                ldmBT(bfr[nn], smem_u32(&Bs[ks + (lane & 15)][wn + 16 * nn + ((lane >> 4) << 3)]));
            #pragma unroll
            for (int mi = 0; mi < 4; mi++)
                #pragma unroll
                for (int ni = 0; ni < 4; ni++)
                    mma16816(acc[mi][ni], af[mi], &bfr[ni >> 1][(ni & 1) << 1]);
        }
        __syncthreads();
    }

    const int g = lane >> 2, t = lane & 3;
    #pragma unroll
    for (int mi = 0; mi < 4; mi++)
        #pragma unroll
        for (int ni = 0; ni < 4; ni++) {
            long row = m0 + wm + 16 * mi + g;
            int  col = n0 + wn + 8 * ni + 2 * t;
            *reinterpret_cast<float2*>(&C[row * (long)ldc + col]) =
                make_float2(acc[mi][ni][0], acc[mi][ni][1]);
            *reinterpret_cast<float2*>(&C[(row + 8) * (long)ldc + col]) =
                make_float2(acc[mi][ni][2], acc[mi][ni][3]);
        }
}

// ---------------- split fp32 -> [hi|hi|lo] bf16 (seq) ----------------
__global__ __launch_bounds__(256) void split_seq(const float* __restrict__ seq)
{
    long i = (long)blockIdx.x * 256 + threadIdx.x;   // over ML_*D_
    int m = (int)(i >> 10), k = (int)(i & 1023);
    float x = seq[i];
    __nv_bfloat16 h = __float2bfloat16_rn(x);
    __nv_bfloat16 l = __float2bfloat16_rn(x - __bfloat162float(h));
    long base = (long)m * K3 + k;
    g_acat[base] = h; g_acat[base + 1024] = h; g_acat[base + 2048] = l;
}

// ---------------- pack weights: B_cat[seg*1024+k][n], segs [hi;lo;hi] ----------------
__global__ __launch_bounds__(256) void pack_w(const float* __restrict__ wq,
                                              const float* __restrict__ wk,
                                              const float* __restrict__ wv,
                                              const float* __restrict__ wg)
{
    long i = (long)blockIdx.x * 256 + threadIdx.x;   // over 1024*4096
    int k = (int)(i >> 12), n = (int)(i & 4095);
    float x;
    if (n < 1024)       x = wq[((n >> 7) << 17) + (k << 7) + (n & 127)];
    else if (n < 2048)  x = wk[(((n - 1024) >> 7) << 17) + (k << 7) + (n & 127)];
    else if (n < 3072)  x = wv[(((n - 2048) >> 7) << 17) + (k << 7) + (n & 127)];
    else                x = wg[(k << 10) + (n - 3072)];
    __nv_bfloat16 h = __float2bfloat16_rn(x);
    __nv_bfloat16 l = __float2bfloat16_rn(x - __bfloat162float(h));
    long base = (long)k * NBIG + n;
    g_bcat[base] = h;
    g_bcat[base + (long)1024 * NBIG] = l;
    g_bcat[base + (long)2048 * NBIG] = h;
}

__global__ __launch_bounds__(256) void pack_wo(const float* __restrict__ wo)
{
    long i = (long)blockIdx.x * 256 + threadIdx.x;   // over 1024*1024
    int k = (int)(i >> 10), n = (int)(i & 1023);
    float x = wo[i];
    __nv_bfloat16 h = __float2bfloat16_rn(x);
    __nv_bfloat16 l = __float2bfloat16_rn(x - __bfloat162float(h));
    long base = (long)k * 1024 + n;
    g_b2[base] = h;
    g_b2[base + 1024L * 1024] = l;
    g_b2[base + 2048L * 1024] = h;
}

// ---------------- RoPE on q (cols 0-1023) and k (cols 1024-2047) of g_c ----------------
__global__ __launch_bounds__(256) void rope_kernel(const float* __restrict__ times)
{
    int idx = blockIdx.x * 256 + threadIdx.x;   // over ML_*8*64
    int p = idx & 63;
    int h = (idx >> 6) & 7;
    int m = idx >> 9;

    float t = times[m];
    float theta = exp2f(-13.287712379549449f * (float)p * (1.0f / 64.0f));
    float s, c;
    sincosf(t * theta, &s, &c);

    long base = (long)m * NBIG + (h << 7) + (p << 1);
    float q0 = g_c[base], q1 = g_c[base + 1];
    g_c[base]     = c * q0 - s * q1;
    g_c[base + 1] = c * q1 + s * q0;
    float k0 = g_c[base + 1024], k1 = g_c[base + 1025];
    g_c[base + 1024] = c * k0 + s * k1;
    g_c[base + 1025] = c * k1 - s * k0;
}

// ---------------- causal retention: O = (Q K^T ⊙ decay) V  (fp32 SIMT) ----------------
__global__ __launch_bounds__(256) void retention_kernel()
{
    const int h  = blockIdx.z;
    const int b  = blockIdx.y;
    const int i0 = blockIdx.x * 64;

    const long rowbase = (long)b * L_;
    const float* Q  = g_c + (h << 7);
    const float* K  = g_c + 1024 + (h << 7);
    const float* Vv = g_c + 2048 + (h << 7);

    const float gamma = 1.0f - exp2f(-5.0f - (float)h);
    const float lg = log2f(gamma);

    const int tid = threadIdx.x;
    const int ty = tid >> 4, tx = tid & 15;

    __shared__ float Ssm[64][72];
    __shared__ float ubuf[2 * 32 * 72];
    float* Qs = ubuf;
    float* Ks = ubuf + 32 * 72;
    float* Vs = ubuf;

    float powr[4], powc[4];
    #pragma unroll
    for (int i = 0; i < 4; i++) {
        powr[i] = exp2f(lg * (float)((ty << 2) + i));
        powc[i] = exp2f(-lg * (float)((tx << 2) + i));
    }

    float oacc[4][8] = {};

    for (int j0 = 0; j0 <= i0; j0 += 64) {
        float sacc[4][4] = {};
        #pragma unroll 1
        for (int kc = 0; kc < QK_; kc += 32) {
            #pragma unroll
            for (int rep = 0; rep < 2; rep++) {
                int idx = tid + rep * 256;
                int m  = idx >> 3;
                int k4 = (idx & 7) << 2;
                float4 qv = *reinterpret_cast<const float4*>(Q + (rowbase + i0 + m) * NBIG + kc + k4);
                Qs[(k4 + 0) * 72 + m] = qv.x; Qs[(k4 + 1) * 72 + m] = qv.y;
                Qs[(k4 + 2) * 72 + m] = qv.z; Qs[(k4 + 3) * 72 + m] = qv.w;
                float4 kv = *reinterpret_cast<const float4*>(K + (rowbase + j0 + m) * NBIG + kc + k4);
                Ks[(k4 + 0) * 72 + m] = kv.x; Ks[(k4 + 1) * 72 + m] = kv.y;
                Ks[(k4 + 2) * 72 + m] = kv.z; Ks[(k4 + 3) * 72 + m] = kv.w;
            }
            __syncthreads();
            #pragma unroll
            for (int kk = 0; kk < 32; kk++) {
                float4 av = *reinterpret_cast<const float4*>(&Qs[kk * 72 + (ty << 2)]);
                float4 bv = *reinterpret_cast<const float4*>(&Ks[kk * 72 + (tx << 2)]);
                float a[4] = {av.x, av.y, av.z, av.w};
                float bb[4] = {bv.x, bv.y, bv.z, bv.w};
                #pragma unroll
                for (int i = 0; i < 4; i++)
                    #pragma unroll
                    for (int j = 0; j < 4; j++)
                        sacc[i][j] += a[i] * bb[j];
            }
            __syncthreads();
        }

        const float base = exp2f(lg * (float)(i0 - j0));
        const bool diag = (j0 == i0);
        #pragma unroll
        for (int i = 0; i < 4; i++) {
            int r = (ty << 2) + i;
            #pragma unroll
            for (int j = 0; j < 4; j++) {
                int c = (tx << 2) + j;
                float sv = sacc[i][j] * (base * powr[i] * powc[j]);
                if (diag && c > r) sv = 0.0f;
                Ssm[r][c] = sv;
            }
        }
        __syncthreads();

        #pragma unroll 1
        for (int vc = 0; vc < 64; vc += 32) {
            #pragma unroll
            for (int rep = 0; rep < 4; rep++) {
                int idx = tid + rep * 256;
                int m  = idx >> 5;
                int k4 = (idx & 31) << 2;
                *reinterpret_cast<float4*>(&Vs[m * 132 + k4]) =
                    *reinterpret_cast<const float4*>(Vv + (rowbase + j0 + vc + m) * NBIG + k4);
            }
            __syncthreads();
            #pragma unroll
            for (int kk = 0; kk < 32; kk++) {
                float a[4];
                #pragma unroll
                for (int i = 0; i < 4; i++) a[i] = Ssm[(ty << 2) + i][vc + kk];
                #pragma unroll
                for (int j = 0; j < 8; j++) {
                    float bvv = Vs[kk * 132 + tx + (j << 4)];
                    #pragma unroll
                    for (int i = 0; i < 4; i++) oacc[i][j] += a[i] * bvv;
                }
            }
            __syncthreads();
        }
    }

    #pragma unroll
    for (int i = 0; i < 4; i++) {
        long row = ((long)(b * L_ + i0 + (ty << 2) + i) * H_ + h);
        #pragma unroll
        for (int j = 0; j < 8; j++)
            g_r[row * V_ + tx + (j << 4)] = oacc[i][j];
    }
}

// ---------------- group norm over V=128 per (b,l,h), in place on g_r ----------------
__global__ __launch_bounds__(256) void gnorm_kernel(const float* __restrict__ gn_w,
                                                    const float* __restrict__ gn_b)
{
    int g    = blockIdx.x * 8 + (threadIdx.x >> 5);
    int lane = threadIdx.x & 31;
    int h    = g & (H_ - 1);

    float* p = g_r + (long)g * V_;
    float4 x = *reinterpret_cast<float4*>(p + (lane << 2));

    float sum = x.x + x.y + x.z + x.w;
    #pragma unroll
    for (int off = 16; off; off >>= 1) sum += __shfl_xor_sync(~0u, sum, off);
    float mean = sum * (1.0f / 128.0f);

    float dx = x.x - mean, dy = x.y - mean, dz = x.z - mean, dw = x.w - mean;
    float sq = dx * dx + dy * dy + dz * dz + dw * dw;
    #pragma unroll
    for (int off = 16; off; off >>= 1) sq += __shfl_xor_sync(~0u, sq, off);
    float inv = rsqrtf(sq * (1.0f / 128.0f) + 1e-5f);

    const float* w  = gn_w + h * V_ + (lane << 2);
    const float* bb = gn_b + h * V_ + (lane << 2);
    x.x = dx * inv * w[0] + bb[0];
    x.y = dy * inv * w[1] + bb[1];
    x.z = dz * inv * w[2] + bb[2];
    x.w = dw * inv * w[3] + bb[3];
    *reinterpret_cast<float4*>(p + (lane << 2)) = x;
}

// ---------------- silu gate * rn, split to bf16 [hi|hi|lo] ----------------
__global__ __launch_bounds__(256) void gate_kernel()
{
    long i = (long)blockIdx.x * 256 + threadIdx.x;   // over ML_*1024
    int m = (int)(i >> 10), c = (int)(i & 1023);
    float gv = g_c[(long)m * NBIG + 3072 + c];
    float sig = 1.0f / (1.0f + expf(-gv));
    float x = gv * sig * g_r[i];
    __nv_bfloat16 h = __float2bfloat16_rn(x);
    __nv_bfloat16 l = __float2bfloat16_rn(x - __bfloat162float(h));
    long base = (long)m * K3 + c;
    g_a2[base] = h; g_a2[base + 1024] = h; g_a2[base + 2048] = l;
}

// ---------------- launch ----------------
extern "C" void kernel_launch(void* const* d_in, const int* in_sizes, int n_in,
                              void* d_out, int out_size)
{
    const float* seq   = (const float*)d_in[0];
    const float* times = (const float*)d_in[1];
    const float* wq    = (const float*)d_in[2];
    const float* wk    = (const float*)d_in[3];
    const float* wv    = (const float*)d_in[4];
    const float* wg    = (const float*)d_in[5];
    const float* wo    = (const float*)d_in[6];
    const float* gnw   = (const float*)d_in[7];
    const float* gnb   = (const float*)d_in[8];
    float* out = (float*)d_out;

    split_seq<<<(ML_ * D_) / 256, 256>>>(seq);
    pack_w<<<(D_ * NBIG) / 256, 256>>>(wq, wk, wv, wg);
    pack_wo<<<(D_ * 1024) / 256, 256>>>(wo);

    // fused q|k|v|g projection: [4096 x 3072] @ [3072 x 4096] -> g_c
    gemm_bf16<<<dim3(NBIG / 128, ML_ / 128), 256>>>(nullptr, 0, K3, NBIG, NBIG);

    rope_kernel<<<(ML_ * H_ * 64) / 256, 256>>>(times);
    retention_kernel<<<dim3(L_ / 64, B_, H_), 256>>>();
    gnorm_kernel<<<(ML_ * H_) / 8, 256>>>(gnw, gnb);
    gate_kernel<<<(ML_ * 1024) / 256, 256>>>();

    // output projection: [4096 x 3072] @ [3072 x 1024] -> d_out
    gemm_bf16<<<dim3(1024 / 128, ML_ / 128), 256>>>(out, 1, K3, 1024, 1024);
}

// round 5
// speedup vs baseline: 2.8514x; 1.6687x over previous
#include <cuda_runtime.h>
#include <cuda_bf16.h>
#include <cstdint>

#define B_ 2
#define L_ 2048
#define D_ 1024
#define H_ 8
#define QK_ 128
#define V_ 128
#define ML_ (B_*L_)        // 4096 rows
#define NBIG 4096          // q|k|v|g column blocks
#define K3 3072            // tripled K for split-bf16

// ---------------- scratch (device globals: no allocation allowed) ----------------
__device__ __nv_bfloat16 g_acat[(long)ML_ * K3];    // seq split [Ah|Ah|Al]
__device__ __nv_bfloat16 g_bcat[(long)K3 * NBIG];   // weights split [Bh;Bl;Bh]
__device__ __nv_bfloat16 g_a2[(long)ML_ * K3];      // gate*rn split
__device__ __nv_bfloat16 g_b2[(long)K3 * 1024];     // w_o split
__device__ float g_c[(long)ML_ * NBIG];             // fused projection output [q|k|v|g]
__device__ float g_r[(long)ML_ * 1024];             // retention result (b,l,h,v)
// hi/lo split, roped q/k and v: layout [(h*B+b)*L + l][128]
__device__ __nv_bfloat16 g_qh[(long)H_*B_*L_*128];
__device__ __nv_bfloat16 g_ql[(long)H_*B_*L_*128];
__device__ __nv_bfloat16 g_kh[(long)H_*B_*L_*128];
__device__ __nv_bfloat16 g_kl[(long)H_*B_*L_*128];
__device__ __nv_bfloat16 g_vh[(long)H_*B_*L_*128];
__device__ __nv_bfloat16 g_vl[(long)H_*B_*L_*128];

// ---------------- mma helpers ----------------
__device__ __forceinline__ uint32_t smem_u32(const void* p) {
    return (uint32_t)__cvta_generic_to_shared(p);
}
__device__ __forceinline__ void ldmA(uint32_t* r, uint32_t addr) {
    asm volatile("ldmatrix.sync.aligned.m8n8.x4.shared.b16 {%0,%1,%2,%3}, [%4];"
                 : "=r"(r[0]), "=r"(r[1]), "=r"(r[2]), "=r"(r[3]) : "r"(addr));
}
__device__ __forceinline__ void ldmBT(uint32_t* r, uint32_t addr) {
    asm volatile("ldmatrix.sync.aligned.m8n8.x4.trans.shared.b16 {%0,%1,%2,%3}, [%4];"
                 : "=r"(r[0]), "=r"(r[1]), "=r"(r[2]), "=r"(r[3]) : "r"(addr));
}
__device__ __forceinline__ void mma16816(float* c, const uint32_t* a, const uint32_t* b) {
    asm volatile("mma.sync.aligned.m16n8k16.row.col.f32.bf16.bf16.f32 "
                 "{%0,%1,%2,%3},{%4,%5,%6,%7},{%8,%9},{%0,%1,%2,%3};"
                 : "+f"(c[0]), "+f"(c[1]), "+f"(c[2]), "+f"(c[3])
                 : "r"(a[0]), "r"(a[1]), "r"(a[2]), "r"(a[3]), "r"(b[0]), "r"(b[1]));
}
__device__ __forceinline__ void cp16(__nv_bfloat16* s, const __nv_bfloat16* gp) {
    uint32_t a = smem_u32(s);
    asm volatile("cp.async.cg.shared.global [%0], [%1], 16;" :: "r"(a), "l"(gp));
}
#define CP_COMMIT() asm volatile("cp.async.commit_group;")
#define CP_WAIT0()  asm volatile("cp.async.wait_group 0;")

// ---------------- bf16 tensor-core GEMM: C[M,N] = A[M,K3] * B[K3,N] ----------------
__global__ __launch_bounds__(256) void gemm_bf16(float* __restrict__ Cext, int which,
                                                 int Kdim, int ldb, int ldc)
{
    const __nv_bfloat16* A = (which == 0) ? g_acat : g_a2;
    const __nv_bfloat16* Bp = (which == 0) ? g_bcat : g_b2;
    float* C = (which == 0) ? g_c : Cext;

    __shared__ __nv_bfloat16 As[128][40];
    __shared__ __nv_bfloat16 Bs[32][136];

    const int tid = threadIdx.x;
    const int warp = tid >> 5, lane = tid & 31;
    const int wm = (warp >> 2) * 64;
    const int wn = (warp & 3) * 32;
    const long m0 = (long)blockIdx.y * 128;
    const int  n0 = blockIdx.x * 128;

    float acc[4][4][4] = {};

    for (int k0 = 0; k0 < Kdim; k0 += 32) {
        #pragma unroll
        for (int rep = 0; rep < 2; rep++) {
            int idx = tid + rep * 256;
            int r  = idx >> 2, cg = (idx & 3) << 3;
            *reinterpret_cast<float4*>(&As[r][cg]) =
                *reinterpret_cast<const float4*>(A + (m0 + r) * (long)Kdim + k0 + cg);
            int rb = idx >> 4, cb = (idx & 15) << 3;
            *reinterpret_cast<float4*>(&Bs[rb][cb]) =
                *reinterpret_cast<const float4*>(Bp + (long)(k0 + rb) * ldb + n0 + cb);
        }
        __syncthreads();
        #pragma unroll
        for (int ks = 0; ks < 32; ks += 16) {
            uint32_t af[4][4], bfr[2][4];
            #pragma unroll
            for (int mi = 0; mi < 4; mi++)
                ldmA(af[mi], smem_u32(&As[wm + 16 * mi + (lane & 15)][ks + ((lane >> 4) << 3)]));
            #pragma unroll
            for (int nn = 0; nn < 2; nn++)
                ldmBT(bfr[nn], smem_u32(&Bs[ks + (lane & 15)][wn + 16 * nn + ((lane >> 4) << 3)]));
            #pragma unroll
            for (int mi = 0; mi < 4; mi++)
                #pragma unroll
                for (int ni = 0; ni < 4; ni++)
                    mma16816(acc[mi][ni], af[mi], &bfr[ni >> 1][(ni & 1) << 1]);
        }
        __syncthreads();
    }

    const int g = lane >> 2, t = lane & 3;
    #pragma unroll
    for (int mi = 0; mi < 4; mi++)
        #pragma unroll
        for (int ni = 0; ni < 4; ni++) {
            long row = m0 + wm + 16 * mi + g;
            int  col = n0 + wn + 8 * ni + 2 * t;
            *reinterpret_cast<float2*>(&C[row * (long)ldc + col]) =
                make_float2(acc[mi][ni][0], acc[mi][ni][1]);
            *reinterpret_cast<float2*>(&C[(row + 8) * (long)ldc + col]) =
                make_float2(acc[mi][ni][2], acc[mi][ni][3]);
        }
}

// ---------------- split fp32 -> [hi|hi|lo] bf16 (seq) ----------------
__global__ __launch_bounds__(256) void split_seq(const float* __restrict__ seq)
{
    long i = (long)blockIdx.x * 256 + threadIdx.x;
    int m = (int)(i >> 10), k = (int)(i & 1023);
    float x = seq[i];
    __nv_bfloat16 h = __float2bfloat16_rn(x);
    __nv_bfloat16 l = __float2bfloat16_rn(x - __bfloat162float(h));
    long base = (long)m * K3 + k;
    g_acat[base] = h; g_acat[base + 1024] = h; g_acat[base + 2048] = l;
}

__global__ __launch_bounds__(256) void pack_w(const float* __restrict__ wq,
                                              const float* __restrict__ wk,
                                              const float* __restrict__ wv,
                                              const float* __restrict__ wg)
{
    long i = (long)blockIdx.x * 256 + threadIdx.x;
    int k = (int)(i >> 12), n = (int)(i & 4095);
    float x;
    if (n < 1024)       x = wq[((n >> 7) << 17) + (k << 7) + (n & 127)];
    else if (n < 2048)  x = wk[(((n - 1024) >> 7) << 17) + (k << 7) + (n & 127)];
    else if (n < 3072)  x = wv[(((n - 2048) >> 7) << 17) + (k << 7) + (n & 127)];
    else                x = wg[(k << 10) + (n - 3072)];
    __nv_bfloat16 h = __float2bfloat16_rn(x);
    __nv_bfloat16 l = __float2bfloat16_rn(x - __bfloat162float(h));
    long base = (long)k * NBIG + n;
    g_bcat[base] = h;
    g_bcat[base + (long)1024 * NBIG] = l;
    g_bcat[base + (long)2048 * NBIG] = h;
}

__global__ __launch_bounds__(256) void pack_wo(const float* __restrict__ wo)
{
    long i = (long)blockIdx.x * 256 + threadIdx.x;
    int k = (int)(i >> 10), n = (int)(i & 1023);
    float x = wo[i];
    __nv_bfloat16 h = __float2bfloat16_rn(x);
    __nv_bfloat16 l = __float2bfloat16_rn(x - __bfloat162float(h));
    long base = (long)k * 1024 + n;
    g_b2[base] = h;
    g_b2[base + 1024L * 1024] = l;
    g_b2[base + 2048L * 1024] = h;
}

// ---------------- prep: rope(q,k) + hi/lo split of q,k,v into retention layout ----------------
__device__ __forceinline__ void split2(__nv_bfloat16* ph, __nv_bfloat16* pl, float x0, float x1)
{
    __nv_bfloat16 h0 = __float2bfloat16_rn(x0), h1 = __float2bfloat16_rn(x1);
    __nv_bfloat16 l0 = __float2bfloat16_rn(x0 - __bfloat162float(h0));
    __nv_bfloat16 l1 = __float2bfloat16_rn(x1 - __bfloat162float(h1));
    __nv_bfloat162 hv; hv.x = h0; hv.y = h1;
    __nv_bfloat162 lv; lv.x = l0; lv.y = l1;
    *reinterpret_cast<__nv_bfloat162*>(ph) = hv;
    *reinterpret_cast<__nv_bfloat162*>(pl) = lv;
}

__global__ __launch_bounds__(256) void prep_kernel(const float* __restrict__ times)
{
    int idx = blockIdx.x * 256 + threadIdx.x;   // over ML_*H_*64
    int p = idx & 63;
    int h = (idx >> 6) & 7;
    int m = idx >> 9;
    int b = m >> 11, l = m & 2047;

    float t = times[m];
    float theta = exp2f(-13.287712379549449f * (float)p * (1.0f / 64.0f));
    float s, c;
    sincosf(t * theta, &s, &c);

    long cb = (long)m * NBIG + (h << 7) + (p << 1);
    float q0 = g_c[cb], q1 = g_c[cb + 1];
    float k0 = g_c[cb + 1024], k1 = g_c[cb + 1025];
    float v0 = g_c[cb + 2048], v1 = g_c[cb + 2049];
    float Q0 = c * q0 - s * q1, Q1 = c * q1 + s * q0;
    float K0 = c * k0 + s * k1, K1 = c * k1 - s * k0;

    long ob = ((long)((h * B_ + b) * L_ + l) << 7) + (p << 1);
    split2(g_qh + ob, g_ql + ob, Q0, Q1);
    split2(g_kh + ob, g_kl + ob, K0, K1);
    split2(g_vh + ob, g_vl + ob, v0, v1);
}

// ---------------- tensor-core retention ----------------
// smem layout (bf16 elems): QH 0, QL 8704, KV double-buffer at 17408 (per buf:
// Kh, Kl, Vh, Vl each 64*136=8704; buf stride 34816), SH 87040, SL 91648.
#define TQ 8704
#define OFF_QL 8704
#define OFF_KV 17408
#define KVSTRIDE 34816
#define OFF_SH 87040
#define OFF_SL 91648
#define RET_SMEM (96256 * 2)

__device__ __forceinline__ void stage_kv(__nv_bfloat16* sm, int buf, int tid,
    const __nv_bfloat16* Kh, const __nv_bfloat16* Kl,
    const __nv_bfloat16* Vh, const __nv_bfloat16* Vl, int j0)
{
    __nv_bfloat16* dst = sm + OFF_KV + buf * KVSTRIDE;
    #pragma unroll
    for (int rep = 0; rep < 4; rep++) {
        int idx = tid + rep * 256;
        int row = idx >> 4, c8 = (idx & 15) << 3;
        long go = (long)(j0 + row) * 128 + c8;
        int so = row * 136 + c8;
        cp16(dst + so,             Kh + go);
        cp16(dst + TQ + so,        Kl + go);
        cp16(dst + 2 * TQ + so,    Vh + go);
        cp16(dst + 3 * TQ + so,    Vl + go);
    }
}

__global__ __launch_bounds__(256) void retention_mma()
{
    extern __shared__ __nv_bfloat16 sm[];
    const int h = blockIdx.z, b = blockIdx.y;
    const int it = gridDim.x - 1 - blockIdx.x;   // heavy tiles first
    const int i0 = it * 64;
    const int nj = it + 1;

    const long hb = (long)(h * B_ + b) * L_ * 128;
    const __nv_bfloat16* Qh = g_qh + hb;
    const __nv_bfloat16* Ql = g_ql + hb;
    const __nv_bfloat16* Kh = g_kh + hb;
    const __nv_bfloat16* Kl = g_kl + hb;
    const __nv_bfloat16* Vh = g_vh + hb;
    const __nv_bfloat16* Vl = g_vl + hb;

    const int tid = threadIdx.x, warp = tid >> 5, lane = tid & 31;
    const int g = lane >> 2, t = lane & 3;

    const float gamma = 1.0f - exp2f(-5.0f - (float)h);
    const float lg = log2f(gamma);

    // QK warp tile 16x32 (4x2 grid); SV warp tile 16x64 (4x2 grid)
    const int wm1 = (warp >> 1) << 4, wn1 = (warp & 1) << 5;
    const int wm2 = wm1,              wn2 = (warp & 1) << 6;

    // block-invariant decay factors
    float pr[2], pc[4][2];
    pr[0] = exp2f(lg * (float)(wm1 + g));
    pr[1] = exp2f(lg * (float)(wm1 + g + 8));
    const float invg = exp2f(-lg);
    #pragma unroll
    for (int ni = 0; ni < 4; ni++) {
        int c0 = wn1 + 8 * ni + 2 * t;
        pc[ni][0] = exp2f(-lg * (float)c0);
        pc[ni][1] = pc[ni][0] * invg;
    }

    // prefetch Q tiles + first K/V tile
    #pragma unroll
    for (int rep = 0; rep < 4; rep++) {
        int idx = tid + rep * 256;
        int row = idx >> 4, c8 = (idx & 15) << 3;
        long go = (long)(i0 + row) * 128 + c8;
        int so = row * 136 + c8;
        cp16(sm + so, Qh + go);
        cp16(sm + OFF_QL + so, Ql + go);
    }
    stage_kv(sm, 0, tid, Kh, Kl, Vh, Vl, 0);
    CP_COMMIT();

    float accO[8][4] = {};
    __nv_bfloat16* sSH = sm + OFF_SH;
    __nv_bfloat16* sSL = sm + OFF_SL;

    for (int jt = 0; jt < nj; jt++) {
        CP_WAIT0();
        __syncthreads();
        int cur = jt & 1;
        if (jt + 1 < nj) { stage_kv(sm, cur ^ 1, tid, Kh, Kl, Vh, Vl, (jt + 1) * 64); CP_COMMIT(); }

        __nv_bfloat16* sKh = sm + OFF_KV + cur * KVSTRIDE;
        __nv_bfloat16* sKl = sKh + TQ;
        __nv_bfloat16* sVh = sKh + 2 * TQ;
        __nv_bfloat16* sVl = sKh + 3 * TQ;

        // ---- S = Q K^T (3 split passes over K=128) ----
        float accS[4][4] = {};
        #pragma unroll
        for (int pass = 0; pass < 3; pass++) {
            const __nv_bfloat16* Ap = (pass == 2) ? (sm + OFF_QL) : sm;
            const __nv_bfloat16* Bp = (pass == 1) ? sKl : sKh;
            #pragma unroll
            for (int k16 = 0; k16 < 8; k16++) {
                uint32_t a[4];
                ldmA(a, smem_u32(Ap + (wm1 + (lane & 15)) * 136 + k16 * 16 + ((lane >> 4) << 3)));
                uint32_t bk[2][4];
                #pragma unroll
                for (int nn = 0; nn < 2; nn++)
                    ldmA(bk[nn], smem_u32(Bp + (wn1 + 16 * nn + (lane & 15)) * 136 + k16 * 16 + ((lane >> 4) << 3)));
                #pragma unroll
                for (int ni = 0; ni < 4; ni++) {
                    // non-trans B from [n][k]: pairs (r0,r2)/(r1,r3)
                    uint32_t bb[2] = { bk[ni >> 1][ni & 1], bk[ni >> 1][(ni & 1) + 2] };
                    mma16816(accS[ni], a, bb);
                }
            }
        }

        // ---- decay + mask, split-store S to smem ----
        const float base = exp2f(lg * (float)((it - jt) * 64));
        const bool diag = (jt == it);
        #pragma unroll
        for (int ni = 0; ni < 4; ni++) {
            int c0 = wn1 + 8 * ni + 2 * t;
            int r0 = wm1 + g;
            float s00 = accS[ni][0] * (base * pr[0] * pc[ni][0]);
            float s01 = accS[ni][1] * (base * pr[0] * pc[ni][1]);
            float s10 = accS[ni][2] * (base * pr[1] * pc[ni][0]);
            float s11 = accS[ni][3] * (base * pr[1] * pc[ni][1]);
            if (diag) {
                if (c0 > r0)         s00 = 0.0f;
                if (c0 + 1 > r0)     s01 = 0.0f;
                if (c0 > r0 + 8)     s10 = 0.0f;
                if (c0 + 1 > r0 + 8) s11 = 0.0f;
            }
            split2(sSH + r0 * 72 + c0,       sSL + r0 * 72 + c0,       s00, s01);
            split2(sSH + (r0 + 8) * 72 + c0, sSL + (r0 + 8) * 72 + c0, s10, s11);
        }
        __syncthreads();

        // ---- O += S V (3 split passes over K=64) ----
        #pragma unroll
        for (int pass = 0; pass < 3; pass++) {
            const __nv_bfloat16* Sp = (pass == 2) ? sSL : sSH;
            const __nv_bfloat16* Vp = (pass == 1) ? sVl : sVh;
            #pragma unroll
            for (int k16 = 0; k16 < 4; k16++) {
                uint32_t a[4];
                ldmA(a, smem_u32(Sp + (wm2 + (lane & 15)) * 72 + k16 * 16 + ((lane >> 4) << 3)));
                uint32_t bv[4][4];
                #pragma unroll
                for (int nn = 0; nn < 4; nn++)
                    ldmBT(bv[nn], smem_u32(Vp + (k16 * 16 + (lane & 15)) * 136 + wn2 + 16 * nn + ((lane >> 4) << 3)));
                #pragma unroll
                for (int ni = 0; ni < 8; ni++)
                    mma16816(accO[ni], a, &bv[ni >> 1][(ni & 1) << 1]);
            }
        }
        __syncthreads();
    }

    // ---- epilogue: write (b,l,h,v) ----
    #pragma unroll
    for (int ni = 0; ni < 8; ni++) {
        long row0 = (long)(b * L_ + i0 + wm2 + g);
        int col = wn2 + 8 * ni + 2 * t;
        *reinterpret_cast<float2*>(&g_r[(row0 * H_ + h) * 128 + col]) =
            make_float2(accO[ni][0], accO[ni][1]);
        *reinterpret_cast<float2*>(&g_r[((row0 + 8) * H_ + h) * 128 + col]) =
            make_float2(accO[ni][2], accO[ni][3]);
    }
}

// ---------------- group norm over V=128 per (b,l,h), in place on g_r ----------------
__global__ __launch_bounds__(256) void gnorm_kernel(const float* __restrict__ gn_w,
                                                    const float* __restrict__ gn_b)
{
    int g    = blockIdx.x * 8 + (threadIdx.x >> 5);
    int lane = threadIdx.x & 31;
    int h    = g & (H_ - 1);

    float* p = g_r + (long)g * V_;
    float4 x = *reinterpret_cast<float4*>(p + (lane << 2));

    float sum = x.x + x.y + x.z + x.w;
    #pragma unroll
    for (int off = 16; off; off >>= 1) sum += __shfl_xor_sync(~0u, sum, off);
    float mean = sum * (1.0f / 128.0f);

    float dx = x.x - mean, dy = x.y - mean, dz = x.z - mean, dw = x.w - mean;
    float sq = dx * dx + dy * dy + dz * dz + dw * dw;
    #pragma unroll
    for (int off = 16; off; off >>= 1) sq += __shfl_xor_sync(~0u, sq, off);
    float inv = rsqrtf(sq * (1.0f / 128.0f) + 1e-5f);

    const float* w  = gn_w + h * V_ + (lane << 2);
    const float* bb = gn_b + h * V_ + (lane << 2);
    x.x = dx * inv * w[0] + bb[0];
    x.y = dy * inv * w[1] + bb[1];
    x.z = dz * inv * w[2] + bb[2];
    x.w = dw * inv * w[3] + bb[3];
    *reinterpret_cast<float4*>(p + (lane << 2)) = x;
}

// ---------------- silu gate * rn, split to bf16 [hi|hi|lo] ----------------
__global__ __launch_bounds__(256) void gate_kernel()
{
    long i = (long)blockIdx.x * 256 + threadIdx.x;
    int m = (int)(i >> 10), c = (int)(i & 1023);
    float gv = g_c[(long)m * NBIG + 3072 + c];
    float sig = 1.0f / (1.0f + expf(-gv));
    float x = gv * sig * g_r[i];
    __nv_bfloat16 h = __float2bfloat16_rn(x);
    __nv_bfloat16 l = __float2bfloat16_rn(x - __bfloat162float(h));
    long base = (long)m * K3 + c;
    g_a2[base] = h; g_a2[base + 1024] = h; g_a2[base + 2048] = l;
}

// ---------------- launch ----------------
extern "C" void kernel_launch(void* const* d_in, const int* in_sizes, int n_in,
                              void* d_out, int out_size)
{
    const float* seq   = (const float*)d_in[0];
    const float* times = (const float*)d_in[1];
    const float* wq    = (const float*)d_in[2];
    const float* wk    = (const float*)d_in[3];
    const float* wv    = (const float*)d_in[4];
    const float* wg    = (const float*)d_in[5];
    const float* wo    = (const float*)d_in[6];
    const float* gnw   = (const float*)d_in[7];
    const float* gnb   = (const float*)d_in[8];
    float* out = (float*)d_out;

    cudaFuncSetAttribute(retention_mma, cudaFuncAttributeMaxDynamicSharedMemorySize, RET_SMEM);

    split_seq<<<(ML_ * D_) / 256, 256>>>(seq);
    pack_w<<<(D_ * NBIG) / 256, 256>>>(wq, wk, wv, wg);
    pack_wo<<<(D_ * 1024) / 256, 256>>>(wo);

    // fused q|k|v|g projection: [4096 x 3072] @ [3072 x 4096] -> g_c
    gemm_bf16<<<dim3(NBIG / 128, ML_ / 128), 256>>>(nullptr, 0, K3, NBIG, NBIG);

    prep_kernel<<<(ML_ * H_ * 64) / 256, 256>>>(times);
    retention_mma<<<dim3(L_ / 64, B_, H_), 256, RET_SMEM>>>();
    gnorm_kernel<<<(ML_ * H_) / 8, 256>>>(gnw, gnb);
    gate_kernel<<<(ML_ * 1024) / 256, 256>>>();

    // output projection: [4096 x 3072] @ [3072 x 1024] -> d_out
    gemm_bf16<<<dim3(1024 / 128, ML_ / 128), 256>>>(out, 1, K3, 1024, 1024);
}

// round 7
// speedup vs baseline: 3.1596x; 1.1081x over previous
#include <cuda_runtime.h>
#include <cuda_bf16.h>
#include <cstdint>

#define B_ 2
#define L_ 2048
#define D_ 1024
#define H_ 8
#define QK_ 128
#define V_ 128
#define ML_ (B_*L_)        // 4096 rows
#define NBIG 4096          // q|k|v|g column blocks
#define K3 3072            // tripled K for split-bf16

// ---------------- scratch (device globals: no allocation allowed) ----------------
__device__ __nv_bfloat16 g_acat[(long)ML_ * K3];    // seq split [Ah|Ah|Al]
__device__ __nv_bfloat16 g_bcat[(long)K3 * NBIG];   // weights split [Bh;Bl;Bh]
__device__ __nv_bfloat16 g_a2[(long)ML_ * K3];      // gate*rn split
__device__ __nv_bfloat16 g_b2[(long)K3 * 1024];     // w_o split
__device__ float g_c[(long)ML_ * NBIG];             // fused projection output [q|k|v|g]
__device__ float g_r[(long)ML_ * 1024];             // retention result (b,l,h,v)
// hi/lo split, roped q/k and v: layout [(h*B+b)*L + l][128]
__device__ __nv_bfloat16 g_qh[(long)H_*B_*L_*128];
__device__ __nv_bfloat16 g_ql[(long)H_*B_*L_*128];
__device__ __nv_bfloat16 g_kh[(long)H_*B_*L_*128];
__device__ __nv_bfloat16 g_kl[(long)H_*B_*L_*128];
__device__ __nv_bfloat16 g_vh[(long)H_*B_*L_*128];
__device__ __nv_bfloat16 g_vl[(long)H_*B_*L_*128];

// ---------------- mma helpers ----------------
__device__ __forceinline__ uint32_t smem_u32(const void* p) {
    return (uint32_t)__cvta_generic_to_shared(p);
}
__device__ __forceinline__ void ldmA(uint32_t* r, uint32_t addr) {
    asm volatile("ldmatrix.sync.aligned.m8n8.x4.shared.b16 {%0,%1,%2,%3}, [%4];"
                 : "=r"(r[0]), "=r"(r[1]), "=r"(r[2]), "=r"(r[3]) : "r"(addr));
}
__device__ __forceinline__ void ldmBT(uint32_t* r, uint32_t addr) {
    asm volatile("ldmatrix.sync.aligned.m8n8.x4.trans.shared.b16 {%0,%1,%2,%3}, [%4];"
                 : "=r"(r[0]), "=r"(r[1]), "=r"(r[2]), "=r"(r[3]) : "r"(addr));
}
__device__ __forceinline__ void mma16816(float* c, const uint32_t* a, const uint32_t* b) {
    asm volatile("mma.sync.aligned.m16n8k16.row.col.f32.bf16.bf16.f32 "
                 "{%0,%1,%2,%3},{%4,%5,%6,%7},{%8,%9},{%0,%1,%2,%3};"
                 : "+f"(c[0]), "+f"(c[1]), "+f"(c[2]), "+f"(c[3])
                 : "r"(a[0]), "r"(a[1]), "r"(a[2]), "r"(a[3]), "r"(b[0]), "r"(b[1]));
}
__device__ __forceinline__ void cp16(__nv_bfloat16* s, const __nv_bfloat16* gp) {
    uint32_t a = smem_u32(s);
    asm volatile("cp.async.cg.shared.global [%0], [%1], 16;" :: "r"(a), "l"(gp));
}
#define CP_COMMIT() asm volatile("cp.async.commit_group;")
#define CP_WAIT0()  asm volatile("cp.async.wait_group 0;")
#define CP_WAIT2()  asm volatile("cp.async.wait_group 2;")

// ---------------- pipelined bf16 tensor-core GEMM: C[M,N] = A[M,K3] * B[K3,N] ----------------
// 128x128 block tile, 8 warps (2x4), 64x32 warp tile, BK=32, 4-stage cp.async.
#define GSTAGES 4
#define G_AS 5120            // 128*40 bf16 per stage
#define G_BS 4352            // 32*136 bf16 per stage
#define G_STAGE (G_AS + G_BS)
#define GEMM_SMEM (GSTAGES * G_STAGE * 2)   // bytes

__global__ __launch_bounds__(256, 2) void gemm_bf16(float* __restrict__ Cext, int which,
                                                    int Kdim, int ldb, int ldc)
{
    extern __shared__ __nv_bfloat16 smg[];
    const __nv_bfloat16* A  = (which == 0) ? g_acat : g_a2;
    const __nv_bfloat16* Bp = (which == 0) ? g_bcat : g_b2;
    float* C = (which == 0) ? g_c : Cext;

    const int tid = threadIdx.x;
    const int warp = tid >> 5, lane = tid & 31;
    const int wm = (warp >> 2) * 64;
    const int wn = (warp & 3) * 32;
    const long m0 = (long)blockIdx.y * 128;
    const int  n0 = blockIdx.x * 128;

    // per-thread load coords (2 chunks of 8 for A and B each)
    const int ar0 = tid >> 2, ac0 = (tid & 3) << 3;          // A: 128x32
    const int br0 = tid >> 4, bc0 = (tid & 15) << 3;         // B: 32x128

    const int KT = Kdim >> 5;

    // prologue: issue GSTAGES-1 stages
    #pragma unroll
    for (int s = 0; s < GSTAGES - 1; s++) {
        __nv_bfloat16* sA = smg + s * G_STAGE;
        __nv_bfloat16* sB = sA + G_AS;
        int k0 = s << 5;
        #pragma unroll
        for (int rep = 0; rep < 2; rep++) {
            int r = ar0 + rep * 64, c = ac0;
            cp16(sA + r * 40 + c, A + (m0 + r) * (long)Kdim + k0 + c);
            int rb = br0 + rep * 16, cb = bc0;
            cp16(sB + rb * 136 + cb, Bp + (long)(k0 + rb) * ldb + n0 + cb);
        }
        CP_COMMIT();
    }

    float acc[4][4][4] = {};

    for (int kt = 0; kt < KT; kt++) {
        CP_WAIT2();
        __syncthreads();

        // issue next stage loads (overlap with compute below)
        int nk = kt + GSTAGES - 1;
        if (nk < KT) {
            __nv_bfloat16* sA = smg + (nk & (GSTAGES - 1)) * G_STAGE;
            __nv_bfloat16* sB = sA + G_AS;
            int k0 = nk << 5;
            #pragma unroll
            for (int rep = 0; rep < 2; rep++) {
                int r = ar0 + rep * 64, c = ac0;
                cp16(sA + r * 40 + c, A + (m0 + r) * (long)Kdim + k0 + c);
                int rb = br0 + rep * 16, cb = bc0;
                cp16(sB + rb * 136 + cb, Bp + (long)(k0 + rb) * ldb + n0 + cb);
            }
            CP_COMMIT();
        }

        __nv_bfloat16* sA = smg + (kt & (GSTAGES - 1)) * G_STAGE;
        __nv_bfloat16* sB = sA + G_AS;

        #pragma unroll
        for (int ks = 0; ks < 32; ks += 16) {
            uint32_t af[4][4], bfr[2][4];
            #pragma unroll
            for (int mi = 0; mi < 4; mi++)
                ldmA(af[mi], smem_u32(sA + (wm + 16 * mi + (lane & 15)) * 40 + ks + ((lane >> 4) << 3)));
            #pragma unroll
            for (int nn = 0; nn < 2; nn++)
                ldmBT(bfr[nn], smem_u32(sB + (ks + (lane & 15)) * 136 + wn + 16 * nn + ((lane >> 4) << 3)));
            #pragma unroll
            for (int mi = 0; mi < 4; mi++)
                #pragma unroll
                for (int ni = 0; ni < 4; ni++)
                    mma16816(acc[mi][ni], af[mi], &bfr[ni >> 1][(ni & 1) << 1]);
        }
        __syncthreads();
    }

    const int g = lane >> 2, t = lane & 3;
    #pragma unroll
    for (int mi = 0; mi < 4; mi++)
        #pragma unroll
        for (int ni = 0; ni < 4; ni++) {
            long row = m0 + wm + 16 * mi + g;
            int  col = n0 + wn + 8 * ni + 2 * t;
            *reinterpret_cast<float2*>(&C[row * (long)ldc + col]) =
                make_float2(acc[mi][ni][0], acc[mi][ni][1]);
            *reinterpret_cast<float2*>(&C[(row + 8) * (long)ldc + col]) =
                make_float2(acc[mi][ni][2], acc[mi][ni][3]);
        }
}

// ---------------- split fp32 -> [hi|hi|lo] bf16 (seq) ----------------
__global__ __launch_bounds__(256) void split_seq(const float* __restrict__ seq)
{
    long i = (long)blockIdx.x * 256 + threadIdx.x;
    int m = (int)(i >> 10), k = (int)(i & 1023);
    float x = seq[i];
    __nv_bfloat16 h = __float2bfloat16_rn(x);
    __nv_bfloat16 l = __float2bfloat16_rn(x - __bfloat162float(h));
    long base = (long)m * K3 + k;
    g_acat[base] = h; g_acat[base + 1024] = h; g_acat[base + 2048] = l;
}

__global__ __launch_bounds__(256) void pack_w(const float* __restrict__ wq,
                                              const float* __restrict__ wk,
                                              const float* __restrict__ wv,
                                              const float* __restrict__ wg)
{
    long i = (long)blockIdx.x * 256 + threadIdx.x;
    int k = (int)(i >> 12), n = (int)(i & 4095);
    float x;
    if (n < 1024)       x = wq[((n >> 7) << 17) + (k << 7) + (n & 127)];
    else if (n < 2048)  x = wk[(((n - 1024) >> 7) << 17) + (k << 7) + (n & 127)];
    else if (n < 3072)  x = wv[(((n - 2048) >> 7) << 17) + (k << 7) + (n & 127)];
    else                x = wg[(k << 10) + (n - 3072)];
    __nv_bfloat16 h = __float2bfloat16_rn(x);
    __nv_bfloat16 l = __float2bfloat16_rn(x - __bfloat162float(h));
    long base = (long)k * NBIG + n;
    g_bcat[base] = h;
    g_bcat[base + (long)1024 * NBIG] = l;
    g_bcat[base + (long)2048 * NBIG] = h;
}

__global__ __launch_bounds__(256) void pack_wo(const float* __restrict__ wo)
{
    long i = (long)blockIdx.x * 256 + threadIdx.x;
    int k = (int)(i >> 10), n = (int)(i & 1023);
    float x = wo[i];
    __nv_bfloat16 h = __float2bfloat16_rn(x);
    __nv_bfloat16 l = __float2bfloat16_rn(x - __bfloat162float(h));
    long base = (long)k * 1024 + n;
    g_b2[base] = h;
    g_b2[base + 1024L * 1024] = l;
    g_b2[base + 2048L * 1024] = h;
}

// ---------------- prep: rope(q,k) + hi/lo split of q,k,v into retention layout ----------------
__device__ __forceinline__ void split2(__nv_bfloat16* ph, __nv_bfloat16* pl, float x0, float x1)
{
    __nv_bfloat16 h0 = __float2bfloat16_rn(x0), h1 = __float2bfloat16_rn(x1);
    __nv_bfloat16 l0 = __float2bfloat16_rn(x0 - __bfloat162float(h0));
    __nv_bfloat16 l1 = __float2bfloat16_rn(x1 - __bfloat162float(h1));
    __nv_bfloat162 hv; hv.x = h0; hv.y = h1;
    __nv_bfloat162 lv; lv.x = l0; lv.y = l1;
    *reinterpret_cast<__nv_bfloat162*>(ph) = hv;
    *reinterpret_cast<__nv_bfloat162*>(pl) = lv;
}

__global__ __launch_bounds__(256) void prep_kernel(const float* __restrict__ times)
{
    int idx = blockIdx.x * 256 + threadIdx.x;   // over ML_*H_*64
    int p = idx & 63;
    int h = (idx >> 6) & 7;
    int m = idx >> 9;
    int b = m >> 11, l = m & 2047;

    float t = times[m];
    float theta = exp2f(-13.287712379549449f * (float)p * (1.0f / 64.0f));
    float s, c;
    sincosf(t * theta, &s, &c);

    long cb = (long)m * NBIG + (h << 7) + (p << 1);
    float q0 = g_c[cb], q1 = g_c[cb + 1];
    float k0 = g_c[cb + 1024], k1 = g_c[cb + 1025];
    float v0 = g_c[cb + 2048], v1 = g_c[cb + 2049];
    float Q0 = c * q0 - s * q1, Q1 = c * q1 + s * q0;
    float K0 = c * k0 + s * k1, K1 = c * k1 - s * k0;

    long ob = ((long)((h * B_ + b) * L_ + l) << 7) + (p << 1);
    split2(g_qh + ob, g_ql + ob, Q0, Q1);
    split2(g_kh + ob, g_kl + ob, K0, K1);
    split2(g_vh + ob, g_vl + ob, v0, v1);
}

// ---------------- tensor-core retention ----------------
#define TQ 8704
#define OFF_QL 8704
#define OFF_KV 17408
#define KVSTRIDE 34816
#define OFF_SH 87040
#define OFF_SL 91648
#define RET_SMEM (96256 * 2)

__device__ __forceinline__ void stage_kv(__nv_bfloat16* sm, int buf, int tid,
    const __nv_bfloat16* Kh, const __nv_bfloat16* Kl,
    const __nv_bfloat16* Vh, const __nv_bfloat16* Vl, int j0)
{
    __nv_bfloat16* dst = sm + OFF_KV + buf * KVSTRIDE;
    #pragma unroll
    for (int rep = 0; rep < 4; rep++) {
        int idx = tid + rep * 256;
        int row = idx >> 4, c8 = (idx & 15) << 3;
        long go = (long)(j0 + row) * 128 + c8;
        int so = row * 136 + c8;
        cp16(dst + so,             Kh + go);
        cp16(dst + TQ + so,        Kl + go);
        cp16(dst + 2 * TQ + so,    Vh + go);
        cp16(dst + 3 * TQ + so,    Vl + go);
    }
}

__global__ __launch_bounds__(256) void retention_mma()
{
    extern __shared__ __nv_bfloat16 sm[];
    const int h = blockIdx.z, b = blockIdx.y;
    const int it = gridDim.x - 1 - blockIdx.x;   // heavy tiles first
    const int i0 = it * 64;
    const int nj = it + 1;

    const long hb = (long)(h * B_ + b) * L_ * 128;
    const __nv_bfloat16* Qh = g_qh + hb;
    const __nv_bfloat16* Ql = g_ql + hb;
    const __nv_bfloat16* Kh = g_kh + hb;
    const __nv_bfloat16* Kl = g_kl + hb;
    const __nv_bfloat16* Vh = g_vh + hb;
    const __nv_bfloat16* Vl = g_vl + hb;

    const int tid = threadIdx.x, warp = tid >> 5, lane = tid & 31;
    const int g = lane >> 2, t = lane & 3;

    const float gamma = 1.0f - exp2f(-5.0f - (float)h);
    const float lg = log2f(gamma);

    const int wm1 = (warp >> 1) << 4, wn1 = (warp & 1) << 5;
    const int wm2 = wm1,              wn2 = (warp & 1) << 6;

    float pr[2], pc[4][2];
    pr[0] = exp2f(lg * (float)(wm1 + g));
    pr[1] = exp2f(lg * (float)(wm1 + g + 8));
    const float invg = exp2f(-lg);
    #pragma unroll
    for (int ni = 0; ni < 4; ni++) {
        int c0 = wn1 + 8 * ni + 2 * t;
        pc[ni][0] = exp2f(-lg * (float)c0);
        pc[ni][1] = pc[ni][0] * invg;
    }

    #pragma unroll
    for (int rep = 0; rep < 4; rep++) {
        int idx = tid + rep * 256;
        int row = idx >> 4, c8 = (idx & 15) << 3;
        long go = (long)(i0 + row) * 128 + c8;
        int so = row * 136 + c8;
        cp16(sm + so, Qh + go);
        cp16(sm + OFF_QL + so, Ql + go);
    }
    stage_kv(sm, 0, tid, Kh, Kl, Vh, Vl, 0);
    CP_COMMIT();

    float accO[8][4] = {};
    __nv_bfloat16* sSH = sm + OFF_SH;
    __nv_bfloat16* sSL = sm + OFF_SL;

    for (int jt = 0; jt < nj; jt++) {
        CP_WAIT0();
        __syncthreads();
        int cur = jt & 1;
        if (jt + 1 < nj) { stage_kv(sm, cur ^ 1, tid, Kh, Kl, Vh, Vl, (jt + 1) * 64); CP_COMMIT(); }

        __nv_bfloat16* sKh = sm + OFF_KV + cur * KVSTRIDE;
        __nv_bfloat16* sKl = sKh + TQ;
        __nv_bfloat16* sVh = sKh + 2 * TQ;
        __nv_bfloat16* sVl = sKh + 3 * TQ;

        float accS[4][4] = {};
        #pragma unroll
        for (int pass = 0; pass < 3; pass++) {
            const __nv_bfloat16* Ap = (pass == 2) ? (sm + OFF_QL) : sm;
            const __nv_bfloat16* Bp = (pass == 1) ? sKl : sKh;
            #pragma unroll
            for (int k16 = 0; k16 < 8; k16++) {
                uint32_t a[4];
                ldmA(a, smem_u32(Ap + (wm1 + (lane & 15)) * 136 + k16 * 16 + ((lane >> 4) << 3)));
                uint32_t bk[2][4];
                #pragma unroll
                for (int nn = 0; nn < 2; nn++)
                    ldmA(bk[nn], smem_u32(Bp + (wn1 + 16 * nn + (lane & 15)) * 136 + k16 * 16 + ((lane >> 4) << 3)));
                #pragma unroll
                for (int ni = 0; ni < 4; ni++) {
                    uint32_t bb[2] = { bk[ni >> 1][ni & 1], bk[ni >> 1][(ni & 1) + 2] };
                    mma16816(accS[ni], a, bb);
                }
            }
        }

        const float base = exp2f(lg * (float)((it - jt) * 64));
        const bool diag = (jt == it);
        #pragma unroll
        for (int ni = 0; ni < 4; ni++) {
            int c0 = wn1 + 8 * ni + 2 * t;
            int r0 = wm1 + g;
            float s00 = accS[ni][0] * (base * pr[0] * pc[ni][0]);
            float s01 = accS[ni][1] * (base * pr[0] * pc[ni][1]);
            float s10 = accS[ni][2] * (base * pr[1] * pc[ni][0]);
            float s11 = accS[ni][3] * (base * pr[1] * pc[ni][1]);
            if (diag) {
                if (c0 > r0)         s00 = 0.0f;
                if (c0 + 1 > r0)     s01 = 0.0f;
                if (c0 > r0 + 8)     s10 = 0.0f;
                if (c0 + 1 > r0 + 8) s11 = 0.0f;
            }
            split2(sSH + r0 * 72 + c0,       sSL + r0 * 72 + c0,       s00, s01);
            split2(sSH + (r0 + 8) * 72 + c0, sSL + (r0 + 8) * 72 + c0, s10, s11);
        }
        __syncthreads();

        #pragma unroll
        for (int pass = 0; pass < 3; pass++) {
            const __nv_bfloat16* Sp = (pass == 2) ? sSL : sSH;
            const __nv_bfloat16* Vp = (pass == 1) ? sVl : sVh;
            #pragma unroll
            for (int k16 = 0; k16 < 4; k16++) {
                uint32_t a[4];
                ldmA(a, smem_u32(Sp + (wm2 + (lane & 15)) * 72 + k16 * 16 + ((lane >> 4) << 3)));
                uint32_t bv[4][4];
                #pragma unroll
                for (int nn = 0; nn < 4; nn++)
                    ldmBT(bv[nn], smem_u32(Vp + (k16 * 16 + (lane & 15)) * 136 + wn2 + 16 * nn + ((lane >> 4) << 3)));
                #pragma unroll
                for (int ni = 0; ni < 8; ni++)
                    mma16816(accO[ni], a, &bv[ni >> 1][(ni & 1) << 1]);
            }
        }
        __syncthreads();
    }

    #pragma unroll
    for (int ni = 0; ni < 8; ni++) {
        long row0 = (long)(b * L_ + i0 + wm2 + g);
        int col = wn2 + 8 * ni + 2 * t;
        *reinterpret_cast<float2*>(&g_r[(row0 * H_ + h) * 128 + col]) =
            make_float2(accO[ni][0], accO[ni][1]);
        *reinterpret_cast<float2*>(&g_r[((row0 + 8) * H_ + h) * 128 + col]) =
            make_float2(accO[ni][2], accO[ni][3]);
    }
}

// ---------------- group norm over V=128 per (b,l,h), in place on g_r ----------------
__global__ __launch_bounds__(256) void gnorm_kernel(const float* __restrict__ gn_w,
                                                    const float* __restrict__ gn_b)
{
    int g    = blockIdx.x * 8 + (threadIdx.x >> 5);
    int lane = threadIdx.x & 31;
    int h    = g & (H_ - 1);

    float* p = g_r + (long)g * V_;
    float4 x = *reinterpret_cast<float4*>(p + (lane << 2));

    float sum = x.x + x.y + x.z + x.w;
    #pragma unroll
    for (int off = 16; off; off >>= 1) sum += __shfl_xor_sync(~0u, sum, off);
    float mean = sum * (1.0f / 128.0f);

    float dx = x.x - mean, dy = x.y - mean, dz = x.z - mean, dw = x.w - mean;
    float sq = dx * dx + dy * dy + dz * dz + dw * dw;
    #pragma unroll
    for (int off = 16; off; off >>= 1) sq += __shfl_xor_sync(~0u, sq, off);
    float inv = rsqrtf(sq * (1.0f / 128.0f) + 1e-5f);

    const float* w  = gn_w + h * V_ + (lane << 2);
    const float* bb = gn_b + h * V_ + (lane << 2);
    x.x = dx * inv * w[0] + bb[0];
    x.y = dy * inv * w[1] + bb[1];
    x.z = dz * inv * w[2] + bb[2];
    x.w = dw * inv * w[3] + bb[3];
    *reinterpret_cast<float4*>(p + (lane << 2)) = x;
}

// ---------------- silu gate * rn, split to bf16 [hi|hi|lo] ----------------
__global__ __launch_bounds__(256) void gate_kernel()
{
    long i = (long)blockIdx.x * 256 + threadIdx.x;
    int m = (int)(i >> 10), c = (int)(i & 1023);
    float gv = g_c[(long)m * NBIG + 3072 + c];
    float sig = 1.0f / (1.0f + expf(-gv));
    float x = gv * sig * g_r[i];
    __nv_bfloat16 h = __float2bfloat16_rn(x);
    __nv_bfloat16 l = __float2bfloat16_rn(x - __bfloat162float(h));
    long base = (long)m * K3 + c;
    g_a2[base] = h; g_a2[base + 1024] = h; g_a2[base + 2048] = l;
}

// ---------------- launch ----------------
extern "C" void kernel_launch(void* const* d_in, const int* in_sizes, int n_in,
                              void* d_out, int out_size)
{
    const float* seq   = (const float*)d_in[0];
    const float* times = (const float*)d_in[1];
    const float* wq    = (const float*)d_in[2];
    const float* wk    = (const float*)d_in[3];
    const float* wv    = (const float*)d_in[4];
    const float* wg    = (const float*)d_in[5];
    const float* wo    = (const float*)d_in[6];
    const float* gnw   = (const float*)d_in[7];
    const float* gnb   = (const float*)d_in[8];
    float* out = (float*)d_out;

    cudaFuncSetAttribute(retention_mma, cudaFuncAttributeMaxDynamicSharedMemorySize, RET_SMEM);
    cudaFuncSetAttribute(gemm_bf16, cudaFuncAttributeMaxDynamicSharedMemorySize, GEMM_SMEM);

    split_seq<<<(ML_ * D_) / 256, 256>>>(seq);
    pack_w<<<(D_ * NBIG) / 256, 256>>>(wq, wk, wv, wg);
    pack_wo<<<(D_ * 1024) / 256, 256>>>(wo);

    // fused q|k|v|g projection: [4096 x 3072] @ [3072 x 4096] -> g_c
    gemm_bf16<<<dim3(NBIG / 128, ML_ / 128), 256, GEMM_SMEM>>>(nullptr, 0, K3, NBIG, NBIG);

    prep_kernel<<<(ML_ * H_ * 64) / 256, 256>>>(times);
    retention_mma<<<dim3(L_ / 64, B_, H_), 256, RET_SMEM>>>();
    gnorm_kernel<<<(ML_ * H_) / 8, 256>>>(gnw, gnb);
    gate_kernel<<<(ML_ * 1024) / 256, 256>>>();

    // output projection: [4096 x 3072] @ [3072 x 1024] -> d_out
    gemm_bf16<<<dim3(1024 / 128, ML_ / 128), 256, GEMM_SMEM>>>(out, 1, K3, 1024, 1024);
}

// round 15
// speedup vs baseline: 3.3316x; 1.0544x over previous
#include <cuda_runtime.h>
#include <cuda_bf16.h>
#include <cstdint>

#define B_ 2
#define L_ 2048
#define D_ 1024
#define H_ 8
#define QK_ 128
#define V_ 128
#define ML_ (B_*L_)        // 4096 rows
#define NBIG 4096          // q|k|v|g column blocks
#define K3 3072            // tripled K for split-bf16

// ---------------- scratch (device globals: no allocation allowed) ----------------
__device__ __nv_bfloat16 g_acat[(long)ML_ * K3];    // seq split [Ah|Ah|Al]
__device__ __nv_bfloat16 g_bcat[(long)K3 * NBIG];   // weights split [Bh;Bl;Bh], [k][n]
__device__ __nv_bfloat16 g_a2[(long)ML_ * K3];      // gate*rn split
__device__ __nv_bfloat16 g_b2[(long)K3 * 1024];     // w_o split, [k][n]
__device__ float g_c[(long)ML_ * NBIG];             // fused projection output [q|k|v|g]
__device__ float g_r[(long)ML_ * 1024];             // retention result (b,l,h,v)
// hi/lo split, roped q/k and v: layout [(h*B+b)*L + l][128]
__device__ __nv_bfloat16 g_qh[(long)H_*B_*L_*128];
__device__ __nv_bfloat16 g_ql[(long)H_*B_*L_*128];
__device__ __nv_bfloat16 g_kh[(long)H_*B_*L_*128];
__device__ __nv_bfloat16 g_kl[(long)H_*B_*L_*128];
__device__ __nv_bfloat16 g_vh[(long)H_*B_*L_*128];
__device__ __nv_bfloat16 g_vl[(long)H_*B_*L_*128];

// ---------------- mma helpers ----------------
__device__ __forceinline__ uint32_t smem_u32(const void* p) {
    return (uint32_t)__cvta_generic_to_shared(p);
}
__device__ __forceinline__ void ldmA(uint32_t* r, uint32_t addr) {
    asm volatile("ldmatrix.sync.aligned.m8n8.x4.shared.b16 {%0,%1,%2,%3}, [%4];"
                 : "=r"(r[0]), "=r"(r[1]), "=r"(r[2]), "=r"(r[3]) : "r"(addr));
}
__device__ __forceinline__ void ldmBT(uint32_t* r, uint32_t addr) {
    asm volatile("ldmatrix.sync.aligned.m8n8.x4.trans.shared.b16 {%0,%1,%2,%3}, [%4];"
                 : "=r"(r[0]), "=r"(r[1]), "=r"(r[2]), "=r"(r[3]) : "r"(addr));
}
__device__ __forceinline__ void mma16816(float* c, const uint32_t* a, const uint32_t* b) {
    asm volatile("mma.sync.aligned.m16n8k16.row.col.f32.bf16.bf16.f32 "
                 "{%0,%1,%2,%3},{%4,%5,%6,%7},{%8,%9},{%0,%1,%2,%3};"
                 : "+f"(c[0]), "+f"(c[1]), "+f"(c[2]), "+f"(c[3])
                 : "r"(a[0]), "r"(a[1]), "r"(a[2]), "r"(a[3]), "r"(b[0]), "r"(b[1]));
}
__device__ __forceinline__ void cp16(void* s, const void* gp) {
    uint32_t a = smem_u32(s);
    asm volatile("cp.async.cg.shared.global [%0], [%1], 16;" :: "r"(a), "l"(gp));
}
#define CP_COMMIT() asm volatile("cp.async.commit_group;")
#define CP_WAIT0()  asm volatile("cp.async.wait_group 0;")
#define CP_WAIT1()  asm volatile("cp.async.wait_group 1;")

// ---------------- pipelined bf16 tensor-core GEMM: C[M,N] = A[M,K3] * B[K3,N] ----------------
// 128x128 block tile, 8 warps (2x4), 64x32 warp tile, BK=64, 3-stage cp.async,
// single barrier per slab (trailing sync proven redundant at >=3 stages).
#define GSTAGES 3
#define G_AS 9216            // 128*72 bf16 per stage (A, pitch 72)
#define G_BS 8704            // 64*136 bf16 per stage (B, pitch 136)
#define G_STAGE (G_AS + G_BS)
#define GEMM_SMEM (GSTAGES * G_STAGE * 2)   // 107520 bytes

__device__ __forceinline__ void g_stage(__nv_bfloat16* smg, int buf, int tid,
    const __nv_bfloat16* A, const __nv_bfloat16* Bp, long m0, int n0, int Kdim, int ldb, int k0)
{
    __nv_bfloat16* sA = smg + buf * G_STAGE;
    __nv_bfloat16* sB = sA + G_AS;
    #pragma unroll
    for (int rep = 0; rep < 4; rep++) {            // A: 128 rows x 64 cols
        int idx = tid + rep * 256;
        int r = idx >> 3, c = (idx & 7) << 3;
        cp16(sA + r * 72 + c, A + (m0 + r) * (long)Kdim + k0 + c);
    }
    #pragma unroll
    for (int rep = 0; rep < 4; rep++) {            // B: 64 rows x 128 cols
        int idx = tid + rep * 256;
        int r = idx >> 4, c = (idx & 15) << 3;
        cp16(sB + r * 136 + c, Bp + (long)(k0 + r) * ldb + n0 + c);
    }
}

__global__ __launch_bounds__(256, 2) void gemm_bf16(float* __restrict__ Cext, int which,
                                                    int Kdim, int ldb, int ldc)
{
    extern __shared__ __nv_bfloat16 smg[];
    const __nv_bfloat16* A  = (which == 0) ? g_acat : g_a2;
    const __nv_bfloat16* Bp = (which == 0) ? g_bcat : g_b2;
    float* C = (which == 0) ? g_c : Cext;

    const int tid = threadIdx.x;
    const int warp = tid >> 5, lane = tid & 31;
    const int wm = (warp >> 2) * 64;
    const int wn = (warp & 3) * 32;
    const long m0 = (long)blockIdx.y * 128;
    const int  n0 = blockIdx.x * 128;

    const int KT = Kdim >> 6;   // 48 slabs of 64

    g_stage(smg, 0, tid, A, Bp, m0, n0, Kdim, ldb, 0);
    CP_COMMIT();
    g_stage(smg, 1, tid, A, Bp, m0, n0, Kdim, ldb, 64);
    CP_COMMIT();

    float acc[4][4][4] = {};
    int buf = 0;

    for (int kt = 0; kt < KT; kt++) {
        if (kt < KT - 1) CP_WAIT1(); else CP_WAIT0();
        __syncthreads();

        int nk = kt + 2;
        if (nk < KT) {
            int nb = buf + 2; if (nb >= GSTAGES) nb -= GSTAGES;
            g_stage(smg, nb, tid, A, Bp, m0, n0, Kdim, ldb, nk << 6);
            CP_COMMIT();
        }

        __nv_bfloat16* sA = smg + buf * G_STAGE;
        __nv_bfloat16* sB = sA + G_AS;

        #pragma unroll
        for (int ks = 0; ks < 64; ks += 16) {
            uint32_t af[4][4], bfr[2][4];
            #pragma unroll
            for (int mi = 0; mi < 4; mi++)
                ldmA(af[mi], smem_u32(sA + (wm + 16 * mi + (lane & 15)) * 72 + ks + ((lane >> 4) << 3)));
            #pragma unroll
            for (int nn = 0; nn < 2; nn++)
                ldmBT(bfr[nn], smem_u32(sB + (ks + (lane & 15)) * 136 + wn + 16 * nn + ((lane >> 4) << 3)));
            #pragma unroll
            for (int mi = 0; mi < 4; mi++)
                #pragma unroll
                for (int ni = 0; ni < 4; ni++)
                    mma16816(acc[mi][ni], af[mi], &bfr[ni >> 1][(ni & 1) << 1]);
        }
        // no trailing sync: next iteration's top barrier orders buffer reuse
        if (++buf == GSTAGES) buf = 0;
    }

    const int g = lane >> 2, t = lane & 3;
    #pragma unroll
    for (int mi = 0; mi < 4; mi++)
        #pragma unroll
        for (int ni = 0; ni < 4; ni++) {
            long row = m0 + wm + 16 * mi + g;
            int  col = n0 + wn + 8 * ni + 2 * t;
            *reinterpret_cast<float2*>(&C[row * (long)ldc + col]) =
                make_float2(acc[mi][ni][0], acc[mi][ni][1]);
            *reinterpret_cast<float2*>(&C[(row + 8) * (long)ldc + col]) =
                make_float2(acc[mi][ni][2], acc[mi][ni][3]);
        }
}

// ---------------- split fp32 -> [hi|hi|lo] bf16 (seq) ----------------
__global__ __launch_bounds__(256) void split_seq(const float* __restrict__ seq)
{
    long i = (long)blockIdx.x * 256 + threadIdx.x;
    int m = (int)(i >> 10), k = (int)(i & 1023);
    float x = seq[i];
    __nv_bfloat16 h = __float2bfloat16_rn(x);
    __nv_bfloat16 l = __float2bfloat16_rn(x - __bfloat162float(h));
    long base = (long)m * K3 + k;
    g_acat[base] = h; g_acat[base + 1024] = h; g_acat[base + 2048] = l;
}

__global__ __launch_bounds__(256) void pack_w(const float* __restrict__ wq,
                                              const float* __restrict__ wk,
                                              const float* __restrict__ wv,
                                              const float* __restrict__ wg)
{
    long i = (long)blockIdx.x * 256 + threadIdx.x;
    int k = (int)(i >> 12), n = (int)(i & 4095);
    float x;
    if (n < 1024)       x = wq[((n >> 7) << 17) + (k << 7) + (n & 127)];
    else if (n < 2048)  x = wk[(((n - 1024) >> 7) << 17) + (k << 7) + (n & 127)];
    else if (n < 3072)  x = wv[(((n - 2048) >> 7) << 17) + (k << 7) + (n & 127)];
    else                x = wg[(k << 10) + (n - 3072)];
    __nv_bfloat16 h = __float2bfloat16_rn(x);
    __nv_bfloat16 l = __float2bfloat16_rn(x - __bfloat162float(h));
    long base = (long)k * NBIG + n;
    g_bcat[base] = h;
    g_bcat[base + (long)1024 * NBIG] = l;
    g_bcat[base + (long)2048 * NBIG] = h;
}

__global__ __launch_bounds__(256) void pack_wo(const float* __restrict__ wo)
{
    long i = (long)blockIdx.x * 256 + threadIdx.x;
    int k = (int)(i >> 10), n = (int)(i & 1023);
    float x = wo[i];
    __nv_bfloat16 h = __float2bfloat16_rn(x);
    __nv_bfloat16 l = __float2bfloat16_rn(x - __bfloat162float(h));
    long base = (long)k * 1024 + n;
    g_b2[base] = h;
    g_b2[base + 1024L * 1024] = l;
    g_b2[base + 2048L * 1024] = h;
}

// ---------------- prep: rope(q,k) + hi/lo split of q,k,v into retention layout ----------------
__device__ __forceinline__ void split2(__nv_bfloat16* ph, __nv_bfloat16* pl, float x0, float x1)
{
    __nv_bfloat16 h0 = __float2bfloat16_rn(x0), h1 = __float2bfloat16_rn(x1);
    __nv_bfloat16 l0 = __float2bfloat16_rn(x0 - __bfloat162float(h0));
    __nv_bfloat16 l1 = __float2bfloat16_rn(x1 - __bfloat162float(h1));
    __nv_bfloat162 hv; hv.x = h0; hv.y = h1;
    __nv_bfloat162 lv; lv.x = l0; lv.y = l1;
    *reinterpret_cast<__nv_bfloat162*>(ph) = hv;
    *reinterpret_cast<__nv_bfloat162*>(pl) = lv;
}

__global__ __launch_bounds__(256) void prep_kernel(const float* __restrict__ times)
{
    int idx = blockIdx.x * 256 + threadIdx.x;   // over ML_*H_*64
    int p = idx & 63;
    int h = (idx >> 6) & 7;
    int m = idx >> 9;
    int b = m >> 11, l = m & 2047;

    float t = times[m];
    float theta = exp2f(-13.287712379549449f * (float)p * (1.0f / 64.0f));
    float s, c;
    sincosf(t * theta, &s, &c);

    long cb = (long)m * NBIG + (h << 7) + (p << 1);
    float q0 = g_c[cb], q1 = g_c[cb + 1];
    float k0 = g_c[cb + 1024], k1 = g_c[cb + 1025];
    float v0 = g_c[cb + 2048], v1 = g_c[cb + 2049];
    float Q0 = c * q0 - s * q1, Q1 = c * q1 + s * q0;
    float K0 = c * k0 + s * k1, K1 = c * k1 - s * k0;

    long ob = ((long)((h * B_ + b) * L_ + l) << 7) + (p << 1);
    split2(g_qh + ob, g_ql + ob, Q0, Q1);
    split2(g_kh + ob, g_kl + ob, K0, K1);
    split2(g_vh + ob, g_vl + ob, v0, v1);
}

// ---------------- tensor-core retention (unchanged, proven) ----------------
#define TQ 8704
#define OFF_QL 8704
#define OFF_KV 17408
#define KVSTRIDE 34816
#define OFF_SH 87040
#define OFF_SL 91648
#define RET_SMEM (96256 * 2)

__device__ __forceinline__ void stage_kv(__nv_bfloat16* sm, int buf, int tid,
    const __nv_bfloat16* Kh, const __nv_bfloat16* Kl,
    const __nv_bfloat16* Vh, const __nv_bfloat16* Vl, int j0)
{
    __nv_bfloat16* dst = sm + OFF_KV + buf * KVSTRIDE;
    #pragma unroll
    for (int rep = 0; rep < 4; rep++) {
        int idx = tid + rep * 256;
        int row = idx >> 4, c8 = (idx & 15) << 3;
        long go = (long)(j0 + row) * 128 + c8;
        int so = row * 136 + c8;
        cp16(dst + so,          Kh + go);
        cp16(dst + TQ + so,     Kl + go);
        cp16(dst + 2 * TQ + so, Vh + go);
        cp16(dst + 3 * TQ + so, Vl + go);
    }
}

__global__ __launch_bounds__(256) void retention_mma()
{
    extern __shared__ __nv_bfloat16 sm[];
    const int h = blockIdx.z, b = blockIdx.y;
    const int it = gridDim.x - 1 - blockIdx.x;   // heavy tiles first
    const int i0 = it * 64;
    const int nj = it + 1;

    const long hb = (long)(h * B_ + b) * L_ * 128;
    const __nv_bfloat16* Qh = g_qh + hb;
    const __nv_bfloat16* Ql = g_ql + hb;
    const __nv_bfloat16* Kh = g_kh + hb;
    const __nv_bfloat16* Kl = g_kl + hb;
    const __nv_bfloat16* Vh = g_vh + hb;
    const __nv_bfloat16* Vl = g_vl + hb;

    const int tid = threadIdx.x, warp = tid >> 5, lane = tid & 31;
    const int g = lane >> 2, t = lane & 3;

    const float gamma = 1.0f - exp2f(-5.0f - (float)h);
    const float lg = log2f(gamma);

    const int wm1 = (warp >> 1) << 4, wn1 = (warp & 1) << 5;
    const int wm2 = wm1,              wn2 = (warp & 1) << 6;

    float pr[2], pc[4][2];
    pr[0] = exp2f(lg * (float)(wm1 + g));
    pr[1] = exp2f(lg * (float)(wm1 + g + 8));
    const float invg = exp2f(-lg);
    #pragma unroll
    for (int ni = 0; ni < 4; ni++) {
        int c0 = wn1 + 8 * ni + 2 * t;
        pc[ni][0] = exp2f(-lg * (float)c0);
        pc[ni][1] = pc[ni][0] * invg;
    }

    #pragma unroll
    for (int rep = 0; rep < 4; rep++) {
        int idx = tid + rep * 256;
        int row = idx >> 4, c8 = (idx & 15) << 3;
        long go = (long)(i0 + row) * 128 + c8;
        int so = row * 136 + c8;
        cp16(sm + so, Qh + go);
        cp16(sm + OFF_QL + so, Ql + go);
    }
    stage_kv(sm, 0, tid, Kh, Kl, Vh, Vl, 0);
    CP_COMMIT();

    float accO[8][4] = {};
    __nv_bfloat16* sSH = sm + OFF_SH;
    __nv_bfloat16* sSL = sm + OFF_SL;

    for (int jt = 0; jt < nj; jt++) {
        CP_WAIT0();
        __syncthreads();
        int cur = jt & 1;
        if (jt + 1 < nj) { stage_kv(sm, cur ^ 1, tid, Kh, Kl, Vh, Vl, (jt + 1) * 64); CP_COMMIT(); }

        __nv_bfloat16* sKh = sm + OFF_KV + cur * KVSTRIDE;
        __nv_bfloat16* sKl = sKh + TQ;
        __nv_bfloat16* sVh = sKh + 2 * TQ;
        __nv_bfloat16* sVl = sKh + 3 * TQ;

        float accS[4][4] = {};
        #pragma unroll
        for (int pass = 0; pass < 3; pass++) {
            const __nv_bfloat16* Ap = (pass == 2) ? (sm + OFF_QL) : sm;
            const __nv_bfloat16* Bp = (pass == 1) ? sKl : sKh;
            #pragma unroll
            for (int k16 = 0; k16 < 8; k16++) {
                uint32_t a[4];
                ldmA(a, smem_u32(Ap + (wm1 + (lane & 15)) * 136 + k16 * 16 + ((lane >> 4) << 3)));
                uint32_t bk[2][4];
                #pragma unroll
                for (int nn = 0; nn < 2; nn++)
                    ldmA(bk[nn], smem_u32(Bp + (wn1 + 16 * nn + (lane & 15)) * 136 + k16 * 16 + ((lane >> 4) << 3)));
                #pragma unroll
                for (int ni = 0; ni < 4; ni++) {
                    uint32_t bb[2] = { bk[ni >> 1][ni & 1], bk[ni >> 1][(ni & 1) + 2] };
                    mma16816(accS[ni], a, bb);
                }
            }
        }

        const float base = exp2f(lg * (float)((it - jt) * 64));
        const bool diag = (jt == it);
        #pragma unroll
        for (int ni = 0; ni < 4; ni++) {
            int c0 = wn1 + 8 * ni + 2 * t;
            int r0 = wm1 + g;
            float s00 = accS[ni][0] * (base * pr[0] * pc[ni][0]);
            float s01 = accS[ni][1] * (base * pr[0] * pc[ni][1]);
            float s10 = accS[ni][2] * (base * pr[1] * pc[ni][0]);
            float s11 = accS[ni][3] * (base * pr[1] * pc[ni][1]);
            if (diag) {
                if (c0 > r0)         s00 = 0.0f;
                if (c0 + 1 > r0)     s01 = 0.0f;
                if (c0 > r0 + 8)     s10 = 0.0f;
                if (c0 + 1 > r0 + 8) s11 = 0.0f;
            }
            split2(sSH + r0 * 72 + c0,       sSL + r0 * 72 + c0,       s00, s01);
            split2(sSH + (r0 + 8) * 72 + c0, sSL + (r0 + 8) * 72 + c0, s10, s11);
        }
        __syncthreads();

        #pragma unroll
        for (int pass = 0; pass < 3; pass++) {
            const __nv_bfloat16* Sp = (pass == 2) ? sSL : sSH;
            const __nv_bfloat16* Vp = (pass == 1) ? sVl : sVh;
            #pragma unroll
            for (int k16 = 0; k16 < 4; k16++) {
                uint32_t a[4];
                ldmA(a, smem_u32(Sp + (wm2 + (lane & 15)) * 72 + k16 * 16 + ((lane >> 4) << 3)));
                uint32_t bv[4][4];
                #pragma unroll
                for (int nn = 0; nn < 4; nn++)
                    ldmBT(bv[nn], smem_u32(Vp + (k16 * 16 + (lane & 15)) * 136 + wn2 + 16 * nn + ((lane >> 4) << 3)));
                #pragma unroll
                for (int ni = 0; ni < 8; ni++)
                    mma16816(accO[ni], a, &bv[ni >> 1][(ni & 1) << 1]);
            }
        }
        __syncthreads();
    }

    #pragma unroll
    for (int ni = 0; ni < 8; ni++) {
        long row0 = (long)(b * L_ + i0 + wm2 + g);
        int col = wn2 + 8 * ni + 2 * t;
        *reinterpret_cast<float2*>(&g_r[(row0 * H_ + h) * 128 + col]) =
            make_float2(accO[ni][0], accO[ni][1]);
        *reinterpret_cast<float2*>(&g_r[((row0 + 8) * H_ + h) * 128 + col]) =
            make_float2(accO[ni][2], accO[ni][3]);
    }
}

// ---------------- fused groupnorm + silu gate + bf16 split ----------------
// one warp per (b,l,h) group of 128 values
__global__ __launch_bounds__(256) void gnorm_gate_kernel(const float* __restrict__ gn_w,
                                                         const float* __restrict__ gn_b)
{
    int gidx = blockIdx.x * 8 + (threadIdx.x >> 5);   // group in [0, ML_*H_)
    int lane = threadIdx.x & 31;
    int h    = gidx & (H_ - 1);
    int m    = gidx >> 3;

    const float* p = g_r + (long)gidx * V_;
    float4 x = *reinterpret_cast<const float4*>(p + (lane << 2));

    float sum = x.x + x.y + x.z + x.w;
    #pragma unroll
    for (int off = 16; off; off >>= 1) sum += __shfl_xor_sync(~0u, sum, off);
    float mean = sum * (1.0f / 128.0f);

    float dx = x.x - mean, dy = x.y - mean, dz = x.z - mean, dw = x.w - mean;
    float sq = dx * dx + dy * dy + dz * dz + dw * dw;
    #pragma unroll
    for (int off = 16; off; off >>= 1) sq += __shfl_xor_sync(~0u, sq, off);
    float inv = rsqrtf(sq * (1.0f / 128.0f) + 1e-5f);

    const float* w  = gn_w + h * V_ + (lane << 2);
    const float* bb = gn_b + h * V_ + (lane << 2);
    float rn[4];
    rn[0] = dx * inv * w[0] + bb[0];
    rn[1] = dy * inv * w[1] + bb[1];
    rn[2] = dz * inv * w[2] + bb[2];
    rn[3] = dw * inv * w[3] + bb[3];

    // gate: g_c[m][3072 + h*128 + col]
    const float* gp = g_c + (long)m * NBIG + 3072 + (h << 7) + (lane << 2);
    long base = (long)m * K3 + (h << 7) + (lane << 2);
    #pragma unroll
    for (int j = 0; j < 4; j += 2) {
        float gv0 = gp[j],     gv1 = gp[j + 1];
        float x0 = gv0 * rn[j]     / (1.0f + expf(-gv0));
        float x1 = gv1 * rn[j + 1] / (1.0f + expf(-gv1));
        split2(g_a2 + base + j + 1024, g_a2 + base + j + 2048, x0, x1);  // hi(dup), lo
        __nv_bfloat16 h0 = __float2bfloat16_rn(x0), h1 = __float2bfloat16_rn(x1);
        __nv_bfloat162 hv; hv.x = h0; hv.y = h1;
        *reinterpret_cast<__nv_bfloat162*>(g_a2 + base + j) = hv;
    }
}

// ---------------- launch ----------------
extern "C" void kernel_launch(void* const* d_in, const int* in_sizes, int n_in,
                              void* d_out, int out_size)
{
    const float* seq   = (const float*)d_in[0];
    const float* times = (const float*)d_in[1];
    const float* wq    = (const float*)d_in[2];
    const float* wk    = (const float*)d_in[3];
    const float* wv    = (const float*)d_in[4];
    const float* wg    = (const float*)d_in[5];
    const float* wo    = (const float*)d_in[6];
    const float* gnw   = (const float*)d_in[7];
    const float* gnb   = (const float*)d_in[8];
    float* out = (float*)d_out;

    cudaFuncSetAttribute(retention_mma, cudaFuncAttributeMaxDynamicSharedMemorySize, RET_SMEM);
    cudaFuncSetAttribute(gemm_bf16, cudaFuncAttributeMaxDynamicSharedMemorySize, GEMM_SMEM);

    split_seq<<<(ML_ * D_) / 256, 256>>>(seq);
    pack_w<<<(D_ * NBIG) / 256, 256>>>(wq, wk, wv, wg);
    pack_wo<<<(D_ * 1024) / 256, 256>>>(wo);

    // fused q|k|v|g projection: [4096 x 3072] @ [3072 x 4096] -> g_c
    gemm_bf16<<<dim3(NBIG / 128, ML_ / 128), 256, GEMM_SMEM>>>(nullptr, 0, K3, NBIG, NBIG);

    prep_kernel<<<(ML_ * H_ * 64) / 256, 256>>>(times);
    retention_mma<<<dim3(L_ / 64, B_, H_), 256, RET_SMEM>>>();
    gnorm_gate_kernel<<<(ML_ * H_) / 8, 256>>>(gnw, gnb);

    // output projection: [4096 x 3072] @ [3072 x 1024] -> d_out
    gemm_bf16<<<dim3(1024 / 128, ML_ / 128), 256, GEMM_SMEM>>>(out, 1, K3, 1024, 1024);
}